// round 4
// baseline (speedup 1.0000x reference)
#include <cuda_runtime.h>

// ---------------- problem constants ----------------
#define N_NODES 50000
#define N_EDGES 800000
#define IN_CH   128
#define HID     256
#define OUT_CH  40

// ---------------- device scratch (no allocation anywhere) ----------------
__device__ float g_z [N_NODES * HID];   // z buffer (also reused for logits)
__device__ float g_t [N_NODES * HID];   // MLP intermediate
__device__ float g_h1[N_NODES * HID];
__device__ float g_h2[N_NODES * HID];
__device__ int   g_is32;                // edge_index element width flag

// compile-time buffer binding (no runtime pointer switching, no host symbol use)
template <int S>
__device__ __forceinline__ float* bufptr() {
    if constexpr (S == 0) return g_z;
    else if constexpr (S == 1) return g_t;
    else if constexpr (S == 2) return g_h1;
    else return g_h2;
}

// ---------------- edge dtype probe ----------------
// If the buffer really is int64, every sampled value lies in [0, N_NODES).
// If it is int32, the int64 view packs two random indices -> >= 2^32 a.s.
__global__ void detect_kernel(const long long* __restrict__ ei) {
    if (threadIdx.x == 0) g_is32 = 0;
    __syncthreads();
    long long v = ei[threadIdx.x];           // first 256 values, in bounds either way
    if (v < 0 || v >= N_NODES) atomicOr(&g_is32, 1);
}

__device__ __forceinline__ void load_edge(const void* eiv, int e, int& src, int& dst) {
    if (g_is32) {
        const int* p = (const int*)eiv;
        src = p[e];
        dst = p[N_EDGES + e];
    } else {
        const long long* p = (const long long*)eiv;
        src = (int)p[e];
        dst = (int)p[N_EDGES + e];
    }
}

// ---------------- z = h (self term) ----------------
template <int CH, int HSEL, int ZSEL>
__global__ void copy_self_kernel(const float* __restrict__ hp) {
    const float* h = (HSEL < 0) ? hp : (const float*)bufptr<HSEL>();
    float* z = bufptr<ZSEL>();
    size_t i = (size_t)blockIdx.x * blockDim.x + threadIdx.x;
    size_t total = (size_t)N_NODES * CH / 4;
    if (i < total) ((float4*)z)[i] = ((const float4*)h)[i];
}

// ---------------- z[dst] += h[src] over edges (one warp per edge) ----------------
template <int CH, int HSEL, int ZSEL>
__global__ void scatter_add_kernel(const float* __restrict__ hp,
                                   const void* __restrict__ eiv) {
    const float* h = (HSEL < 0) ? hp : (const float*)bufptr<HSEL>();
    float* z = bufptr<ZSEL>();
    int warp = (blockIdx.x * blockDim.x + threadIdx.x) >> 5;
    int lane = threadIdx.x & 31;
    if (warp >= N_EDGES) return;
    int src, dst;
    load_edge(eiv, warp, src, dst);
    const float* hs = h + (size_t)src * CH;
    float* zd = z + (size_t)dst * CH;
    #pragma unroll
    for (int c = lane; c < CH; c += 32)
        atomicAdd(zd + c, hs[c]);
}

// ---------------- fp32 tiled GEMM: C = act(A @ B + bias) ----------------
// BM=128, BN=64, BK=16, 256 threads, 8x4 microtile.
// CAT: A = concat(g_h1, g_h2) along K (each half row-stride 256).
template <int K, int N, int ASEL, int CSEL, bool CAT, bool RELU>
__global__ void __launch_bounds__(256)
gemm_kernel(const float* __restrict__ B, const float* __restrict__ bias) {
    const float* A = CAT ? (const float*)g_h1 : (const float*)bufptr<ASEL>();
    float* C = bufptr<CSEL>();

    __shared__ float As[16][128];
    __shared__ float Bs[16][64];
    int tid = threadIdx.x;
    int tx = tid & 15;        // 4 cols each
    int ty = tid >> 4;        // 8 rows each
    int m0 = blockIdx.y * 128;
    int n0 = blockIdx.x * 64;

    float acc[8][4];
    #pragma unroll
    for (int i = 0; i < 8; i++)
        #pragma unroll
        for (int j = 0; j < 4; j++) acc[i][j] = 0.f;

    for (int kt = 0; kt < K / 16; kt++) {
        // A tile: 128x16, stored transposed As[k][m]
        #pragma unroll
        for (int l = 0; l < 2; l++) {
            int idx = tid + l * 256;
            int row = idx >> 2;          // 0..127
            int c4  = (idx & 3) * 4;     // 0,4,8,12
            int m = m0 + row;
            int kk = kt * 16 + c4;
            float4 v = make_float4(0.f, 0.f, 0.f, 0.f);
            if (m < N_NODES) {
                if (CAT) {
                    const float* srcp = (kk < 256)
                        ? ((const float*)g_h1 + (size_t)m * 256 + kk)
                        : ((const float*)g_h2 + (size_t)m * 256 + (kk - 256));
                    v = *(const float4*)srcp;
                } else {
                    v = *(const float4*)(A + (size_t)m * K + kk);
                }
            }
            As[c4 + 0][row] = v.x;
            As[c4 + 1][row] = v.y;
            As[c4 + 2][row] = v.z;
            As[c4 + 3][row] = v.w;
        }
        // B tile: 16x64
        {
            int r  = tid >> 4;
            int c4 = (tid & 15) * 4;
            float4 v = make_float4(0.f, 0.f, 0.f, 0.f);
            int col = n0 + c4;
            if (col < N) v = *(const float4*)(B + (size_t)(kt * 16 + r) * N + col);
            *(float4*)&Bs[r][c4] = v;
        }
        __syncthreads();

        #pragma unroll
        for (int k = 0; k < 16; k++) {
            float4 a0 = *(const float4*)&As[k][ty * 8];
            float4 a1 = *(const float4*)&As[k][ty * 8 + 4];
            float4 b  = *(const float4*)&Bs[k][tx * 4];
            float ar[8] = {a0.x, a0.y, a0.z, a0.w, a1.x, a1.y, a1.z, a1.w};
            float br[4] = {b.x, b.y, b.z, b.w};
            #pragma unroll
            for (int i = 0; i < 8; i++)
                #pragma unroll
                for (int j = 0; j < 4; j++)
                    acc[i][j] += ar[i] * br[j];
        }
        __syncthreads();
    }

    int colBase = n0 + tx * 4;
    float4 bv = make_float4(0.f, 0.f, 0.f, 0.f);
    if (colBase < N) bv = *(const float4*)(bias + colBase);
    #pragma unroll
    for (int i = 0; i < 8; i++) {
        int m = m0 + ty * 8 + i;
        if (m < N_NODES && colBase < N) {
            float4 o;
            o.x = acc[i][0] + bv.x;
            o.y = acc[i][1] + bv.y;
            o.z = acc[i][2] + bv.z;
            o.w = acc[i][3] + bv.w;
            if (RELU) {
                o.x = fmaxf(o.x, 0.f); o.y = fmaxf(o.y, 0.f);
                o.z = fmaxf(o.z, 0.f); o.w = fmaxf(o.w, 0.f);
            }
            *(float4*)(C + (size_t)m * N + colBase) = o;
        }
    }
}

// ---------------- log_softmax over 40 logits, one thread per node ----------------
__global__ void logsoftmax_kernel(float* __restrict__ out) {
    int n = blockIdx.x * blockDim.x + threadIdx.x;
    if (n >= N_NODES) return;
    const float* row = (const float*)g_z + (size_t)n * OUT_CH;
    float m = -3.0e38f;
    #pragma unroll
    for (int c = 0; c < OUT_CH; c++) m = fmaxf(m, row[c]);
    float s = 0.f;
    #pragma unroll
    for (int c = 0; c < OUT_CH; c++) s += expf(row[c] - m);
    float lse = m + logf(s);
    float* o = out + (size_t)n * OUT_CH;
    #pragma unroll
    for (int c = 0; c < OUT_CH; c++) o[c] = row[c] - lse;
}

// ---------------- launch ----------------
extern "C" void kernel_launch(void* const* d_in, const int* in_sizes, int n_in,
                              void* d_out, int out_size) {
    const float* x    = (const float*)d_in[0];
    const void*  ei   = (const void*)d_in[1];
    const float* W1a  = (const float*)d_in[2];
    const float* b1a  = (const float*)d_in[3];
    const float* W2a  = (const float*)d_in[4];
    const float* b2a  = (const float*)d_in[5];
    const float* W1b  = (const float*)d_in[6];
    const float* b1b  = (const float*)d_in[7];
    const float* W2b  = (const float*)d_in[8];
    const float* b2b  = (const float*)d_in[9];
    const float* Wlin = (const float*)d_in[10];
    const float* blin = (const float*)d_in[11];
    float* out = (float*)d_out;

    detect_kernel<<<1, 256>>>((const long long*)ei);

    dim3 gemmGrid(HID / 64, (N_NODES + 127) / 128);   // (4, 391)
    dim3 linGrid(1, (N_NODES + 127) / 128);           // (1, 391)
    int edgeBlocks = (N_EDGES * 32 + 255) / 256;      // one warp per edge

    // ---- layer 1: z = x + agg(x); t = relu(z@W1a+b1a); h1 = relu(t@W2a+b2a)
    copy_self_kernel<IN_CH, -1, 0><<<(N_NODES * IN_CH / 4 + 255) / 256, 256>>>(x);
    scatter_add_kernel<IN_CH, -1, 0><<<edgeBlocks, 256>>>(x, ei);
    gemm_kernel<IN_CH, HID, 0, 1, false, true><<<gemmGrid, 256>>>(W1a, b1a);
    gemm_kernel<HID,   HID, 1, 2, false, true><<<gemmGrid, 256>>>(W2a, b2a);

    // ---- layer 2: z = h1 + agg(h1); t = relu(z@W1b+b1b); h2 = relu(t@W2b+b2b)
    copy_self_kernel<HID, 2, 0><<<(N_NODES * HID / 4 + 255) / 256, 256>>>(nullptr);
    scatter_add_kernel<HID, 2, 0><<<edgeBlocks, 256>>>(nullptr, ei);
    gemm_kernel<HID, HID, 0, 1, false, true><<<gemmGrid, 256>>>(W1b, b1b);
    gemm_kernel<HID, HID, 1, 3, false, true><<<gemmGrid, 256>>>(W2b, b2b);

    // ---- readout: logits = concat(h1,h2) @ Wlin + blin  (into g_z, stride 40)
    gemm_kernel<2 * HID, OUT_CH, 0, 0, true, false><<<linGrid, 256>>>(Wlin, blin);
    logsoftmax_kernel<<<(N_NODES + 255) / 256, 256>>>(out);
}

// round 5
// speedup vs baseline: 1.3364x; 1.3364x over previous
#include <cuda_runtime.h>
#include <cuda_bf16.h>
#include <cstdint>

// ---------------- problem constants ----------------
#define N_NODES 50000
#define N_EDGES 800000
#define IN_CH   128
#define HID     256
#define OUT_CH  40

// ---------------- device scratch (no allocation anywhere) ----------------
__device__ float g_z [N_NODES * HID];   // z buffer (also reused for logits)
__device__ float g_t [N_NODES * HID];   // MLP intermediate
__device__ float g_h1[N_NODES * HID];
__device__ float g_h2[N_NODES * HID];
__device__ int   g_is32;                // edge_index element width flag

template <int S>
__device__ __forceinline__ float* bufptr() {
    if constexpr (S == 0) return g_z;
    else if constexpr (S == 1) return g_t;
    else if constexpr (S == 2) return g_h1;
    else return g_h2;
}

// ---------------- edge dtype probe ----------------
__global__ void detect_kernel(const long long* __restrict__ ei) {
    if (threadIdx.x == 0) g_is32 = 0;
    __syncthreads();
    long long v = ei[threadIdx.x];
    if (v < 0 || v >= N_NODES) atomicOr(&g_is32, 1);
}

__device__ __forceinline__ void load_edge(const void* eiv, int e, int& src, int& dst) {
    if (g_is32) {
        const int* p = (const int*)eiv;
        src = p[e];
        dst = p[N_EDGES + e];
    } else {
        const long long* p = (const long long*)eiv;
        src = (int)p[e];
        dst = (int)p[N_EDGES + e];
    }
}

// ---------------- z = h (self term) ----------------
template <int CH, int HSEL, int ZSEL>
__global__ void copy_self_kernel(const float* __restrict__ hp) {
    const float* h = (HSEL < 0) ? hp : (const float*)bufptr<HSEL>();
    float* z = bufptr<ZSEL>();
    size_t i = (size_t)blockIdx.x * blockDim.x + threadIdx.x;
    size_t total = (size_t)N_NODES * CH / 4;
    if (i < total) ((float4*)z)[i] = ((const float4*)h)[i];
}

// ---------------- z[dst] += h[src] over edges (one warp per edge) ----------------
template <int CH, int HSEL, int ZSEL>
__global__ void scatter_add_kernel(const float* __restrict__ hp,
                                   const void* __restrict__ eiv) {
    const float* h = (HSEL < 0) ? hp : (const float*)bufptr<HSEL>();
    float* z = bufptr<ZSEL>();
    int warp = (blockIdx.x * blockDim.x + threadIdx.x) >> 5;
    int lane = threadIdx.x & 31;
    if (warp >= N_EDGES) return;
    int src, dst;
    load_edge(eiv, warp, src, dst);
    const float* hs = h + (size_t)src * CH;
    float* zd = z + (size_t)dst * CH;
    #pragma unroll
    for (int c = lane; c < CH; c += 32)
        atomicAdd(zd + c, hs[c]);
}

// ======================================================================
// Tensor-core GEMM: C[M,256] = act(A[M,K] @ B[K,256] + bias)
// bf16 3-term compensated split (A*B ~= Ah*Bh + Ah*Bl + Al*Bh).
// CTA tile 128x128, 8 warps of 32x64, BK=16, mma.sync m16n8k16.
// ======================================================================
__device__ __forceinline__ void mma_bf16(float* d, uint32_t a0, uint32_t a1,
                                         uint32_t a2, uint32_t a3,
                                         uint32_t b0, uint32_t b1) {
    asm volatile(
        "mma.sync.aligned.m16n8k16.row.col.f32.bf16.bf16.f32 "
        "{%0,%1,%2,%3}, {%4,%5,%6,%7}, {%8,%9}, {%0,%1,%2,%3};\n"
        : "+f"(d[0]), "+f"(d[1]), "+f"(d[2]), "+f"(d[3])
        : "r"(a0), "r"(a1), "r"(a2), "r"(a3), "r"(b0), "r"(b1));
}

__device__ __forceinline__ void split2(float a, float b, uint32_t& hi, uint32_t& lo) {
    __nv_bfloat16 ha = __float2bfloat16(a);
    __nv_bfloat16 hb = __float2bfloat16(b);
    __nv_bfloat16 la = __float2bfloat16(a - __bfloat162float(ha));
    __nv_bfloat16 lb = __float2bfloat16(b - __bfloat162float(hb));
    __nv_bfloat162 h2; h2.x = ha; h2.y = hb;
    __nv_bfloat162 l2; l2.x = la; l2.y = lb;
    hi = *(uint32_t*)&h2;
    lo = *(uint32_t*)&l2;
}

template <int K, int ASEL, int CSEL, bool RELU>
__global__ void __launch_bounds__(256)
mma_gemm_kernel(const float* __restrict__ B, const float* __restrict__ bias) {
    constexpr int N = 256;
    const float* A = bufptr<ASEL>();
    float* C = bufptr<CSEL>();

    // smem tiles, bf16 pairs packed in u32. Row stride 9 u32 (16 bf16 + pad).
    __shared__ uint32_t As_h[128][9], As_l[128][9];
    __shared__ uint32_t Bs_h[128][9], Bs_l[128][9];   // [n][k-pair]

    int tid  = threadIdx.x;
    int wid  = tid >> 5;
    int lane = tid & 31;
    int gid  = lane >> 2;   // group id 0..7
    int tig  = lane & 3;    // thread in group 0..3

    int m0 = blockIdx.y * 128;
    int n0 = blockIdx.x * 128;
    int wm = (wid & 3) * 32;   // warp row base within CTA tile
    int wn = (wid >> 2) * 64;  // warp col base within CTA tile

    float acc[2][8][4];
    #pragma unroll
    for (int mt = 0; mt < 2; mt++)
        #pragma unroll
        for (int nt = 0; nt < 8; nt++)
            #pragma unroll
            for (int r = 0; r < 4; r++) acc[mt][nt][r] = 0.f;

    for (int kt = 0; kt < K / 16; kt++) {
        // ---- A tile: 128 rows x 16 k (fp32 -> bf16 hi/lo), 2 elems/thread/iter
        #pragma unroll
        for (int it = 0; it < 4; it++) {
            int idx = tid + it * 256;         // 0..1023
            int m  = idx >> 3;                // 0..127
            int kw = idx & 7;                 // u32 slot 0..7
            float2 v = make_float2(0.f, 0.f);
            if (m0 + m < N_NODES)
                v = *(const float2*)(A + (size_t)(m0 + m) * K + kt * 16 + kw * 2);
            uint32_t hi, lo;
            split2(v.x, v.y, hi, lo);
            As_h[m][kw] = hi;
            As_l[m][kw] = lo;
        }
        // ---- B tile: 16 k x 128 n, stored transposed [n][k-pair]
        #pragma unroll
        for (int it = 0; it < 4; it++) {
            int idx = tid + it * 256;
            int n  = idx & 127;
            int kw = idx >> 7;                // 0..7
            int krow = kt * 16 + kw * 2;
            float b0 = B[(size_t)krow * N + n0 + n];
            float b1 = B[(size_t)(krow + 1) * N + n0 + n];
            uint32_t hi, lo;
            split2(b0, b1, hi, lo);
            Bs_h[n][kw] = hi;
            Bs_l[n][kw] = lo;
        }
        __syncthreads();

        // ---- fragments + MMA
        uint32_t ah[2][4], al[2][4];
        #pragma unroll
        for (int mt = 0; mt < 2; mt++) {
            int r = wm + mt * 16;
            ah[mt][0] = As_h[r + gid][tig];
            ah[mt][1] = As_h[r + 8 + gid][tig];
            ah[mt][2] = As_h[r + gid][tig + 4];
            ah[mt][3] = As_h[r + 8 + gid][tig + 4];
            al[mt][0] = As_l[r + gid][tig];
            al[mt][1] = As_l[r + 8 + gid][tig];
            al[mt][2] = As_l[r + gid][tig + 4];
            al[mt][3] = As_l[r + 8 + gid][tig + 4];
        }
        #pragma unroll
        for (int nt = 0; nt < 8; nt++) {
            int c = wn + nt * 8 + gid;
            uint32_t bh0 = Bs_h[c][tig],     bh1 = Bs_h[c][tig + 4];
            uint32_t bl0 = Bs_l[c][tig],     bl1 = Bs_l[c][tig + 4];
            #pragma unroll
            for (int mt = 0; mt < 2; mt++) {
                mma_bf16(acc[mt][nt], ah[mt][0], ah[mt][1], ah[mt][2], ah[mt][3], bh0, bh1);
                mma_bf16(acc[mt][nt], al[mt][0], al[mt][1], al[mt][2], al[mt][3], bh0, bh1);
                mma_bf16(acc[mt][nt], ah[mt][0], ah[mt][1], ah[mt][2], ah[mt][3], bl0, bl1);
            }
        }
        __syncthreads();
    }

    // ---- epilogue: bias + relu + store
    #pragma unroll
    for (int nt = 0; nt < 8; nt++) {
        int c = n0 + wn + nt * 8 + tig * 2;
        float bv0 = bias[c], bv1 = bias[c + 1];
        #pragma unroll
        for (int mt = 0; mt < 2; mt++) {
            int r0 = m0 + wm + mt * 16 + gid;
            int r1 = r0 + 8;
            float d0 = acc[mt][nt][0] + bv0;
            float d1 = acc[mt][nt][1] + bv1;
            float d2 = acc[mt][nt][2] + bv0;
            float d3 = acc[mt][nt][3] + bv1;
            if (RELU) {
                d0 = fmaxf(d0, 0.f); d1 = fmaxf(d1, 0.f);
                d2 = fmaxf(d2, 0.f); d3 = fmaxf(d3, 0.f);
            }
            if (r0 < N_NODES) *(float2*)(C + (size_t)r0 * N + c) = make_float2(d0, d1);
            if (r1 < N_NODES) *(float2*)(C + (size_t)r1 * N + c) = make_float2(d2, d3);
        }
    }
}

// ---------------- fp32 SIMT GEMM for readout (K=512 cat, N=40) ----------------
__global__ void __launch_bounds__(256)
readout_gemm_kernel(const float* __restrict__ B, const float* __restrict__ bias) {
    constexpr int K = 512, N = OUT_CH;
    float* C = bufptr<0>();

    __shared__ float As[16][128];
    __shared__ float Bs[16][64];
    int tid = threadIdx.x;
    int tx = tid & 15;
    int ty = tid >> 4;
    int m0 = blockIdx.y * 128;

    float acc[8][4];
    #pragma unroll
    for (int i = 0; i < 8; i++)
        #pragma unroll
        for (int j = 0; j < 4; j++) acc[i][j] = 0.f;

    for (int kt = 0; kt < K / 16; kt++) {
        #pragma unroll
        for (int l = 0; l < 2; l++) {
            int idx = tid + l * 256;
            int row = idx >> 2;
            int c4  = (idx & 3) * 4;
            int m = m0 + row;
            int kk = kt * 16 + c4;
            float4 v = make_float4(0.f, 0.f, 0.f, 0.f);
            if (m < N_NODES) {
                const float* srcp = (kk < 256)
                    ? ((const float*)g_h1 + (size_t)m * 256 + kk)
                    : ((const float*)g_h2 + (size_t)m * 256 + (kk - 256));
                v = *(const float4*)srcp;
            }
            As[c4 + 0][row] = v.x;
            As[c4 + 1][row] = v.y;
            As[c4 + 2][row] = v.z;
            As[c4 + 3][row] = v.w;
        }
        {
            int r  = tid >> 4;
            int c4 = (tid & 15) * 4;
            float4 v = make_float4(0.f, 0.f, 0.f, 0.f);
            if (c4 < N) v = *(const float4*)(B + (size_t)(kt * 16 + r) * N + c4);
            *(float4*)&Bs[r][c4] = v;
        }
        __syncthreads();

        #pragma unroll
        for (int k = 0; k < 16; k++) {
            float4 a0 = *(const float4*)&As[k][ty * 8];
            float4 a1 = *(const float4*)&As[k][ty * 8 + 4];
            float4 b  = *(const float4*)&Bs[k][tx * 4];
            float ar[8] = {a0.x, a0.y, a0.z, a0.w, a1.x, a1.y, a1.z, a1.w};
            float br[4] = {b.x, b.y, b.z, b.w};
            #pragma unroll
            for (int i = 0; i < 8; i++)
                #pragma unroll
                for (int j = 0; j < 4; j++)
                    acc[i][j] += ar[i] * br[j];
        }
        __syncthreads();
    }

    int colBase = tx * 4;
    float4 bv = make_float4(0.f, 0.f, 0.f, 0.f);
    if (colBase < N) bv = *(const float4*)(bias + colBase);
    #pragma unroll
    for (int i = 0; i < 8; i++) {
        int m = m0 + ty * 8 + i;
        if (m < N_NODES && colBase < N) {
            float4 o;
            o.x = acc[i][0] + bv.x;
            o.y = acc[i][1] + bv.y;
            o.z = acc[i][2] + bv.z;
            o.w = acc[i][3] + bv.w;
            *(float4*)(C + (size_t)m * N + colBase) = o;
        }
    }
}

// ---------------- log_softmax over 40 logits, one thread per node ----------------
__global__ void logsoftmax_kernel(float* __restrict__ out) {
    int n = blockIdx.x * blockDim.x + threadIdx.x;
    if (n >= N_NODES) return;
    const float* row = (const float*)g_z + (size_t)n * OUT_CH;
    float m = -3.0e38f;
    #pragma unroll
    for (int c = 0; c < OUT_CH; c++) m = fmaxf(m, row[c]);
    float s = 0.f;
    #pragma unroll
    for (int c = 0; c < OUT_CH; c++) s += expf(row[c] - m);
    float lse = m + logf(s);
    float* o = out + (size_t)n * OUT_CH;
    #pragma unroll
    for (int c = 0; c < OUT_CH; c++) o[c] = row[c] - lse;
}

// ---------------- launch ----------------
extern "C" void kernel_launch(void* const* d_in, const int* in_sizes, int n_in,
                              void* d_out, int out_size) {
    const float* x    = (const float*)d_in[0];
    const void*  ei   = (const void*)d_in[1];
    const float* W1a  = (const float*)d_in[2];
    const float* b1a  = (const float*)d_in[3];
    const float* W2a  = (const float*)d_in[4];
    const float* b2a  = (const float*)d_in[5];
    const float* W1b  = (const float*)d_in[6];
    const float* b1b  = (const float*)d_in[7];
    const float* W2b  = (const float*)d_in[8];
    const float* b2b  = (const float*)d_in[9];
    const float* Wlin = (const float*)d_in[10];
    const float* blin = (const float*)d_in[11];
    float* out = (float*)d_out;

    detect_kernel<<<1, 256>>>((const long long*)ei);

    dim3 mmaGrid(2, (N_NODES + 127) / 128);           // 128x128 tiles over [M,256]
    dim3 linGrid(1, (N_NODES + 127) / 128);
    int edgeBlocks = (N_EDGES * 32 + 255) / 256;

    // ---- layer 1
    copy_self_kernel<IN_CH, -1, 0><<<(N_NODES * IN_CH / 4 + 255) / 256, 256>>>(x);
    scatter_add_kernel<IN_CH, -1, 0><<<edgeBlocks, 256>>>(x, ei);
    mma_gemm_kernel<IN_CH, 0, 1, true><<<mmaGrid, 256>>>(W1a, b1a);
    mma_gemm_kernel<HID,   1, 2, true><<<mmaGrid, 256>>>(W2a, b2a);

    // ---- layer 2
    copy_self_kernel<HID, 2, 0><<<(N_NODES * HID / 4 + 255) / 256, 256>>>(nullptr);
    scatter_add_kernel<HID, 2, 0><<<edgeBlocks, 256>>>(nullptr, ei);
    mma_gemm_kernel<HID, 0, 1, true><<<mmaGrid, 256>>>(W1b, b1b);
    mma_gemm_kernel<HID, 1, 3, true><<<mmaGrid, 256>>>(W2b, b2b);

    // ---- readout + softmax
    readout_gemm_kernel<<<linGrid, 256>>>(Wlin, blin);
    logsoftmax_kernel<<<(N_NODES + 255) / 256, 256>>>(out);
}

// round 6
// speedup vs baseline: 1.3388x; 1.0018x over previous
#include <cuda_runtime.h>
#include <cuda_bf16.h>
#include <cstdint>

// ---------------- problem constants ----------------
#define N_NODES 50000
#define N_EDGES 800000
#define IN_CH   128
#define HID     256
#define OUT_CH  40

// ---------------- device scratch (no allocation anywhere) ----------------
__device__ float g_z [N_NODES * HID];   // z buffer (also reused for logits)
__device__ float g_t [N_NODES * HID];   // MLP intermediate
__device__ float g_h1[N_NODES * HID];
__device__ float g_h2[N_NODES * HID];
__device__ int   g_is32;                // edge_index element width flag

template <int S>
__device__ __forceinline__ float* bufptr() {
    if constexpr (S == 0) return g_z;
    else if constexpr (S == 1) return g_t;
    else if constexpr (S == 2) return g_h1;
    else return g_h2;
}

// ---------------- edge dtype probe ----------------
__global__ void detect_kernel(const long long* __restrict__ ei) {
    if (threadIdx.x == 0) g_is32 = 0;
    __syncthreads();
    long long v = ei[threadIdx.x];
    if (v < 0 || v >= N_NODES) atomicOr(&g_is32, 1);
}

__device__ __forceinline__ void load_edge(const void* eiv, int e, int& src, int& dst) {
    if (g_is32) {
        const int* p = (const int*)eiv;
        src = p[e];
        dst = p[N_EDGES + e];
    } else {
        const long long* p = (const long long*)eiv;
        src = (int)p[e];
        dst = (int)p[N_EDGES + e];
    }
}

// ---------------- z = h (self term) ----------------
template <int CH, int HSEL, int ZSEL>
__global__ void copy_self_kernel(const float* __restrict__ hp) {
    const float* h = (HSEL < 0) ? hp : (const float*)bufptr<HSEL>();
    float* z = bufptr<ZSEL>();
    size_t i = (size_t)blockIdx.x * blockDim.x + threadIdx.x;
    size_t total = (size_t)N_NODES * CH / 4;
    if (i < total) ((float4*)z)[i] = ((const float4*)h)[i];
}

// ---------------- z[dst] += h[src] over edges (one warp per edge) ----------------
template <int CH, int HSEL, int ZSEL>
__global__ void scatter_add_kernel(const float* __restrict__ hp,
                                   const void* __restrict__ eiv) {
    const float* h = (HSEL < 0) ? hp : (const float*)bufptr<HSEL>();
    float* z = bufptr<ZSEL>();
    int warp = (blockIdx.x * blockDim.x + threadIdx.x) >> 5;
    int lane = threadIdx.x & 31;
    if (warp >= N_EDGES) return;
    int src, dst;
    load_edge(eiv, warp, src, dst);
    const float* hs = h + (size_t)src * CH;
    float* zd = z + (size_t)dst * CH;
    #pragma unroll
    for (int c = lane; c < CH; c += 32)
        atomicAdd(zd + c, hs[c]);
}

// ======================================================================
// Tensor-core GEMM: C[M,256] = act(A[M,K] @ B[K,256] + bias)
// bf16 3-term compensated split (A*B ~= Ah*Bh + Ah*Bl + Al*Bh).
// CTA tile 128x128, 8 warps of 32x64, BK=16, mma.sync m16n8k16.
// ======================================================================
__device__ __forceinline__ void mma_bf16(float* d, uint32_t a0, uint32_t a1,
                                         uint32_t a2, uint32_t a3,
                                         uint32_t b0, uint32_t b1) {
    asm volatile(
        "mma.sync.aligned.m16n8k16.row.col.f32.bf16.bf16.f32 "
        "{%0,%1,%2,%3}, {%4,%5,%6,%7}, {%8,%9}, {%0,%1,%2,%3};\n"
        : "+f"(d[0]), "+f"(d[1]), "+f"(d[2]), "+f"(d[3])
        : "r"(a0), "r"(a1), "r"(a2), "r"(a3), "r"(b0), "r"(b1));
}

__device__ __forceinline__ void split2(float a, float b, uint32_t& hi, uint32_t& lo) {
    __nv_bfloat16 ha = __float2bfloat16(a);
    __nv_bfloat16 hb = __float2bfloat16(b);
    __nv_bfloat16 la = __float2bfloat16(a - __bfloat162float(ha));
    __nv_bfloat16 lb = __float2bfloat16(b - __bfloat162float(hb));
    __nv_bfloat162 h2; h2.x = ha; h2.y = hb;
    __nv_bfloat162 l2; l2.x = la; l2.y = lb;
    hi = *(uint32_t*)&h2;
    lo = *(uint32_t*)&l2;
}

template <int K, int ASEL, int CSEL, bool RELU>
__global__ void __launch_bounds__(256)
mma_gemm_kernel(const float* __restrict__ B, const float* __restrict__ bias) {
    constexpr int N = 256;
    const float* A = bufptr<ASEL>();
    float* C = bufptr<CSEL>();

    // smem tiles, bf16 pairs packed in u32. Row stride 9 u32 (16 bf16 + pad).
    __shared__ uint32_t As_h[128][9], As_l[128][9];
    __shared__ uint32_t Bs_h[128][9], Bs_l[128][9];   // [n][k-pair]

    int tid  = threadIdx.x;
    int wid  = tid >> 5;
    int lane = tid & 31;
    int gid  = lane >> 2;   // group id 0..7
    int tig  = lane & 3;    // thread in group 0..3

    int m0 = blockIdx.y * 128;
    int n0 = blockIdx.x * 128;
    int wm = (wid & 3) * 32;   // warp row base within CTA tile
    int wn = (wid >> 2) * 64;  // warp col base within CTA tile

    float acc[2][8][4];
    #pragma unroll
    for (int mt = 0; mt < 2; mt++)
        #pragma unroll
        for (int nt = 0; nt < 8; nt++)
            #pragma unroll
            for (int r = 0; r < 4; r++) acc[mt][nt][r] = 0.f;

    for (int kt = 0; kt < K / 16; kt++) {
        // ---- A tile: 128 rows x 16 k (fp32 -> bf16 hi/lo), 2 elems/thread/iter
        #pragma unroll
        for (int it = 0; it < 4; it++) {
            int idx = tid + it * 256;         // 0..1023
            int m  = idx >> 3;                // 0..127
            int kw = idx & 7;                 // u32 slot 0..7
            float2 v = make_float2(0.f, 0.f);
            if (m0 + m < N_NODES)
                v = *(const float2*)(A + (size_t)(m0 + m) * K + kt * 16 + kw * 2);
            uint32_t hi, lo;
            split2(v.x, v.y, hi, lo);
            As_h[m][kw] = hi;
            As_l[m][kw] = lo;
        }
        // ---- B tile: 16 k x 128 n, stored transposed [n][k-pair]
        #pragma unroll
        for (int it = 0; it < 4; it++) {
            int idx = tid + it * 256;
            int n  = idx & 127;
            int kw = idx >> 7;                // 0..7
            int krow = kt * 16 + kw * 2;
            float b0 = B[(size_t)krow * N + n0 + n];
            float b1 = B[(size_t)(krow + 1) * N + n0 + n];
            uint32_t hi, lo;
            split2(b0, b1, hi, lo);
            Bs_h[n][kw] = hi;
            Bs_l[n][kw] = lo;
        }
        __syncthreads();

        // ---- fragments + MMA
        uint32_t ah[2][4], al[2][4];
        #pragma unroll
        for (int mt = 0; mt < 2; mt++) {
            int r = wm + mt * 16;
            ah[mt][0] = As_h[r + gid][tig];
            ah[mt][1] = As_h[r + 8 + gid][tig];
            ah[mt][2] = As_h[r + gid][tig + 4];
            ah[mt][3] = As_h[r + 8 + gid][tig + 4];
            al[mt][0] = As_l[r + gid][tig];
            al[mt][1] = As_l[r + 8 + gid][tig];
            al[mt][2] = As_l[r + gid][tig + 4];
            al[mt][3] = As_l[r + 8 + gid][tig + 4];
        }
        #pragma unroll
        for (int nt = 0; nt < 8; nt++) {
            int c = wn + nt * 8 + gid;
            uint32_t bh0 = Bs_h[c][tig],     bh1 = Bs_h[c][tig + 4];
            uint32_t bl0 = Bs_l[c][tig],     bl1 = Bs_l[c][tig + 4];
            #pragma unroll
            for (int mt = 0; mt < 2; mt++) {
                mma_bf16(acc[mt][nt], ah[mt][0], ah[mt][1], ah[mt][2], ah[mt][3], bh0, bh1);
                mma_bf16(acc[mt][nt], al[mt][0], al[mt][1], al[mt][2], al[mt][3], bh0, bh1);
                mma_bf16(acc[mt][nt], ah[mt][0], ah[mt][1], ah[mt][2], ah[mt][3], bl0, bl1);
            }
        }
        __syncthreads();
    }

    // ---- epilogue: bias + relu + store
    #pragma unroll
    for (int nt = 0; nt < 8; nt++) {
        int c = n0 + wn + nt * 8 + tig * 2;
        float bv0 = bias[c], bv1 = bias[c + 1];
        #pragma unroll
        for (int mt = 0; mt < 2; mt++) {
            int r0 = m0 + wm + mt * 16 + gid;
            int r1 = r0 + 8;
            float d0 = acc[mt][nt][0] + bv0;
            float d1 = acc[mt][nt][1] + bv1;
            float d2 = acc[mt][nt][2] + bv0;
            float d3 = acc[mt][nt][3] + bv1;
            if (RELU) {
                d0 = fmaxf(d0, 0.f); d1 = fmaxf(d1, 0.f);
                d2 = fmaxf(d2, 0.f); d3 = fmaxf(d3, 0.f);
            }
            if (r0 < N_NODES) *(float2*)(C + (size_t)r0 * N + c) = make_float2(d0, d1);
            if (r1 < N_NODES) *(float2*)(C + (size_t)r1 * N + c) = make_float2(d2, d3);
        }
    }
}

// ---------------- fp32 SIMT GEMM for readout (K=512 cat, N=40) ----------------
__global__ void __launch_bounds__(256)
readout_gemm_kernel(const float* __restrict__ B, const float* __restrict__ bias) {
    constexpr int K = 512, N = OUT_CH;
    float* C = bufptr<0>();

    __shared__ float As[16][128];
    __shared__ float Bs[16][64];
    int tid = threadIdx.x;
    int tx = tid & 15;
    int ty = tid >> 4;
    int m0 = blockIdx.y * 128;

    float acc[8][4];
    #pragma unroll
    for (int i = 0; i < 8; i++)
        #pragma unroll
        for (int j = 0; j < 4; j++) acc[i][j] = 0.f;

    for (int kt = 0; kt < K / 16; kt++) {
        #pragma unroll
        for (int l = 0; l < 2; l++) {
            int idx = tid + l * 256;
            int row = idx >> 2;
            int c4  = (idx & 3) * 4;
            int m = m0 + row;
            int kk = kt * 16 + c4;
            float4 v = make_float4(0.f, 0.f, 0.f, 0.f);
            if (m < N_NODES) {
                const float* srcp = (kk < 256)
                    ? ((const float*)g_h1 + (size_t)m * 256 + kk)
                    : ((const float*)g_h2 + (size_t)m * 256 + (kk - 256));
                v = *(const float4*)srcp;
            }
            As[c4 + 0][row] = v.x;
            As[c4 + 1][row] = v.y;
            As[c4 + 2][row] = v.z;
            As[c4 + 3][row] = v.w;
        }
        {
            int r  = tid >> 4;
            int c4 = (tid & 15) * 4;
            float4 v = make_float4(0.f, 0.f, 0.f, 0.f);
            if (c4 < N) v = *(const float4*)(B + (size_t)(kt * 16 + r) * N + c4);
            *(float4*)&Bs[r][c4] = v;
        }
        __syncthreads();

        #pragma unroll
        for (int k = 0; k < 16; k++) {
            float4 a0 = *(const float4*)&As[k][ty * 8];
            float4 a1 = *(const float4*)&As[k][ty * 8 + 4];
            float4 b  = *(const float4*)&Bs[k][tx * 4];
            float ar[8] = {a0.x, a0.y, a0.z, a0.w, a1.x, a1.y, a1.z, a1.w};
            float br[4] = {b.x, b.y, b.z, b.w};
            #pragma unroll
            for (int i = 0; i < 8; i++)
                #pragma unroll
                for (int j = 0; j < 4; j++)
                    acc[i][j] += ar[i] * br[j];
        }
        __syncthreads();
    }

    int colBase = tx * 4;
    float4 bv = make_float4(0.f, 0.f, 0.f, 0.f);
    if (colBase < N) bv = *(const float4*)(bias + colBase);
    #pragma unroll
    for (int i = 0; i < 8; i++) {
        int m = m0 + ty * 8 + i;
        if (m < N_NODES && colBase < N) {
            float4 o;
            o.x = acc[i][0] + bv.x;
            o.y = acc[i][1] + bv.y;
            o.z = acc[i][2] + bv.z;
            o.w = acc[i][3] + bv.w;
            *(float4*)(C + (size_t)m * N + colBase) = o;
        }
    }
}

// ---------------- log_softmax over 40 logits, one thread per node ----------------
__global__ void logsoftmax_kernel(float* __restrict__ out) {
    int n = blockIdx.x * blockDim.x + threadIdx.x;
    if (n >= N_NODES) return;
    const float* row = (const float*)g_z + (size_t)n * OUT_CH;
    float m = -3.0e38f;
    #pragma unroll
    for (int c = 0; c < OUT_CH; c++) m = fmaxf(m, row[c]);
    float s = 0.f;
    #pragma unroll
    for (int c = 0; c < OUT_CH; c++) s += expf(row[c] - m);
    float lse = m + logf(s);
    float* o = out + (size_t)n * OUT_CH;
    #pragma unroll
    for (int c = 0; c < OUT_CH; c++) o[c] = row[c] - lse;
}

// ---------------- launch ----------------
extern "C" void kernel_launch(void* const* d_in, const int* in_sizes, int n_in,
                              void* d_out, int out_size) {
    const float* x    = (const float*)d_in[0];
    const void*  ei   = (const void*)d_in[1];
    const float* W1a  = (const float*)d_in[2];
    const float* b1a  = (const float*)d_in[3];
    const float* W2a  = (const float*)d_in[4];
    const float* b2a  = (const float*)d_in[5];
    const float* W1b  = (const float*)d_in[6];
    const float* b1b  = (const float*)d_in[7];
    const float* W2b  = (const float*)d_in[8];
    const float* b2b  = (const float*)d_in[9];
    const float* Wlin = (const float*)d_in[10];
    const float* blin = (const float*)d_in[11];
    float* out = (float*)d_out;

    detect_kernel<<<1, 256>>>((const long long*)ei);

    dim3 mmaGrid(2, (N_NODES + 127) / 128);           // 128x128 tiles over [M,256]
    dim3 linGrid(1, (N_NODES + 127) / 128);
    int edgeBlocks = (N_EDGES * 32 + 255) / 256;

    // ---- layer 1
    copy_self_kernel<IN_CH, -1, 0><<<(N_NODES * IN_CH / 4 + 255) / 256, 256>>>(x);
    scatter_add_kernel<IN_CH, -1, 0><<<edgeBlocks, 256>>>(x, ei);
    mma_gemm_kernel<IN_CH, 0, 1, true><<<mmaGrid, 256>>>(W1a, b1a);
    mma_gemm_kernel<HID,   1, 2, true><<<mmaGrid, 256>>>(W2a, b2a);

    // ---- layer 2
    copy_self_kernel<HID, 2, 0><<<(N_NODES * HID / 4 + 255) / 256, 256>>>(nullptr);
    scatter_add_kernel<HID, 2, 0><<<edgeBlocks, 256>>>(nullptr, ei);
    mma_gemm_kernel<HID, 0, 1, true><<<mmaGrid, 256>>>(W1b, b1b);
    mma_gemm_kernel<HID, 1, 3, true><<<mmaGrid, 256>>>(W2b, b2b);

    // ---- readout + softmax
    readout_gemm_kernel<<<linGrid, 256>>>(Wlin, blin);
    logsoftmax_kernel<<<(N_NODES + 255) / 256, 256>>>(out);
}

// round 7
// speedup vs baseline: 1.4869x; 1.1106x over previous
#include <cuda_runtime.h>
#include <cuda_bf16.h>
#include <cstdint>

// ---------------- problem constants ----------------
#define N_NODES 50000
#define N_EDGES 800000
#define IN_CH   128
#define HID     256
#define OUT_CH  40

// ---------------- device scratch (no allocation anywhere) ----------------
__device__ float g_z [N_NODES * HID];   // z buffer (also reused for logits)
__device__ float g_t [N_NODES * HID];   // MLP intermediate
__device__ float g_h1[N_NODES * HID];
__device__ float g_h2[N_NODES * HID];
__device__ int   g_is32;                // edge_index element width flag

template <int S>
__device__ __forceinline__ float* bufptr() {
    if constexpr (S == 0) return g_z;
    else if constexpr (S == 1) return g_t;
    else if constexpr (S == 2) return g_h1;
    else return g_h2;
}

// ---------------- edge dtype probe ----------------
__global__ void detect_kernel(const long long* __restrict__ ei) {
    if (threadIdx.x == 0) g_is32 = 0;
    __syncthreads();
    long long v = ei[threadIdx.x];
    if (v < 0 || v >= N_NODES) atomicOr(&g_is32, 1);
}

__device__ __forceinline__ void load_edge(const void* eiv, int e, int& src, int& dst) {
    if (g_is32) {
        const int* p = (const int*)eiv;
        src = p[e];
        dst = p[N_EDGES + e];
    } else {
        const long long* p = (const long long*)eiv;
        src = (int)p[e];
        dst = (int)p[N_EDGES + e];
    }
}

// ---------------- z = h (self term) ----------------
template <int CH, int HSEL, int ZSEL>
__global__ void copy_self_kernel(const float* __restrict__ hp) {
    const float* h = (HSEL < 0) ? hp : (const float*)bufptr<HSEL>();
    float* z = bufptr<ZSEL>();
    size_t i = (size_t)blockIdx.x * blockDim.x + threadIdx.x;
    size_t total = (size_t)N_NODES * CH / 4;
    if (i < total) ((float4*)z)[i] = ((const float4*)h)[i];
}

// ---------------- z[dst] += h[src] over edges (one warp per edge) ----------------
// float4 hardware reductions (RED.128) — 4x fewer transactions than scalar.
template <int CH, int HSEL, int ZSEL>
__global__ void scatter_add_kernel(const float* __restrict__ hp,
                                   const void* __restrict__ eiv) {
    const float* h = (HSEL < 0) ? hp : (const float*)bufptr<HSEL>();
    float* z = bufptr<ZSEL>();
    int warp = (blockIdx.x * blockDim.x + threadIdx.x) >> 5;
    int lane = threadIdx.x & 31;
    if (warp >= N_EDGES) return;
    int src, dst;
    load_edge(eiv, warp, src, dst);
    const float4* hs = (const float4*)(h + (size_t)src * CH);
    float4* zd = (float4*)(z + (size_t)dst * CH);
    #pragma unroll
    for (int c = lane; c < CH / 4; c += 32) {
        float4 v = __ldg(hs + c);
        atomicAdd(zd + c, v);
    }
}

// ======================================================================
// Tensor-core GEMM: C[M,256] = act(A[M,K] @ B[K,256] + bias)
// bf16 3-term compensated split (A*B ~= Ah*Bh + Ah*Bl + Al*Bh).
// CTA tile 128x128, 8 warps of 32x64, BK=16, mma.sync m16n8k16.
// Double-buffered smem + register prefetch; one syncthreads per K-step.
// ======================================================================
__device__ __forceinline__ void mma_bf16(float* d, uint32_t a0, uint32_t a1,
                                         uint32_t a2, uint32_t a3,
                                         uint32_t b0, uint32_t b1) {
    asm volatile(
        "mma.sync.aligned.m16n8k16.row.col.f32.bf16.bf16.f32 "
        "{%0,%1,%2,%3}, {%4,%5,%6,%7}, {%8,%9}, {%0,%1,%2,%3};\n"
        : "+f"(d[0]), "+f"(d[1]), "+f"(d[2]), "+f"(d[3])
        : "r"(a0), "r"(a1), "r"(a2), "r"(a3), "r"(b0), "r"(b1));
}

__device__ __forceinline__ void split2(float a, float b, uint32_t& hi, uint32_t& lo) {
    __nv_bfloat16 ha = __float2bfloat16(a);
    __nv_bfloat16 hb = __float2bfloat16(b);
    __nv_bfloat16 la = __float2bfloat16(a - __bfloat162float(ha));
    __nv_bfloat16 lb = __float2bfloat16(b - __bfloat162float(hb));
    __nv_bfloat162 h2; h2.x = ha; h2.y = hb;
    __nv_bfloat162 l2; l2.x = la; l2.y = lb;
    hi = *(uint32_t*)&h2;
    lo = *(uint32_t*)&l2;
}

template <int K, int ASEL, int CSEL, bool RELU>
__global__ void __launch_bounds__(256, 2)
mma_gemm_kernel(const float* __restrict__ B, const float* __restrict__ bias) {
    constexpr int N = 256;
    constexpr int KT = K / 16;
    const float* A = bufptr<ASEL>();
    float* C = bufptr<CSEL>();

    // double-buffered smem tiles, bf16 pairs packed in u32; row stride 9 (pad)
    __shared__ uint32_t As_h[2][128][9], As_l[2][128][9];
    __shared__ uint32_t Bs_h[2][128][9], Bs_l[2][128][9];   // [n][k-pair]

    int tid  = threadIdx.x;
    int wid  = tid >> 5;
    int lane = tid & 31;
    int gid  = lane >> 2;   // group id 0..7
    int tig  = lane & 3;    // thread in group 0..3

    int m0 = blockIdx.y * 128;
    int n0 = blockIdx.x * 128;
    int wm = (wid & 3) * 32;   // warp row base
    int wn = (wid >> 2) * 64;  // warp col base

    // per-thread loader coordinates (fixed across K-steps)
    int aM  = tid >> 1;                 // covers rows tid/2 and tid/2 (2 slots/row? see below)
    // A tile: 128 rows x 8 u32-slots = 1024 pairs; thread handles 4 pairs:
    //   idx = tid + it*256 -> m = idx>>3, kw = idx&7
    // B tile: n = idx&127, kw = idx>>7
    (void)aM;

    float2 aReg[4];
    float2 bReg[4];

    // ---- prefetch tile 0 into registers
    {
        #pragma unroll
        for (int it = 0; it < 4; it++) {
            int idx = tid + it * 256;
            int m   = idx >> 3;
            int kw  = idx & 7;
            aReg[it] = make_float2(0.f, 0.f);
            if (m0 + m < N_NODES)
                aReg[it] = *(const float2*)(A + (size_t)(m0 + m) * K + kw * 2);
            int n    = idx & 127;
            int kwb  = idx >> 7;
            int krow = kwb * 2;
            bReg[it].x = __ldg(B + (size_t)krow * N + n0 + n);
            bReg[it].y = __ldg(B + (size_t)(krow + 1) * N + n0 + n);
        }
        // split + store buffer 0
        #pragma unroll
        for (int it = 0; it < 4; it++) {
            int idx = tid + it * 256;
            int m   = idx >> 3;
            int kw  = idx & 7;
            uint32_t hi, lo;
            split2(aReg[it].x, aReg[it].y, hi, lo);
            As_h[0][m][kw] = hi;
            As_l[0][m][kw] = lo;
            int n   = idx & 127;
            int kwb = idx >> 7;
            split2(bReg[it].x, bReg[it].y, hi, lo);
            Bs_h[0][n][kwb] = hi;
            Bs_l[0][n][kwb] = lo;
        }
    }
    __syncthreads();

    float acc[2][8][4];
    #pragma unroll
    for (int mt = 0; mt < 2; mt++)
        #pragma unroll
        for (int nt = 0; nt < 8; nt++)
            #pragma unroll
            for (int r = 0; r < 4; r++) acc[mt][nt][r] = 0.f;

    for (int kt = 0; kt < KT; kt++) {
        int p = kt & 1;
        // ---- issue global loads for next tile (latency hidden by MMA below)
        if (kt + 1 < KT) {
            #pragma unroll
            for (int it = 0; it < 4; it++) {
                int idx = tid + it * 256;
                int m   = idx >> 3;
                int kw  = idx & 7;
                aReg[it] = make_float2(0.f, 0.f);
                if (m0 + m < N_NODES)
                    aReg[it] = *(const float2*)(A + (size_t)(m0 + m) * K + (kt + 1) * 16 + kw * 2);
                int n    = idx & 127;
                int kwb  = idx >> 7;
                int krow = (kt + 1) * 16 + kwb * 2;
                bReg[it].x = __ldg(B + (size_t)krow * N + n0 + n);
                bReg[it].y = __ldg(B + (size_t)(krow + 1) * N + n0 + n);
            }
        }

        // ---- fragments + MMA on buffer p
        uint32_t ah[2][4], al[2][4];
        #pragma unroll
        for (int mt = 0; mt < 2; mt++) {
            int r = wm + mt * 16;
            ah[mt][0] = As_h[p][r + gid][tig];
            ah[mt][1] = As_h[p][r + 8 + gid][tig];
            ah[mt][2] = As_h[p][r + gid][tig + 4];
            ah[mt][3] = As_h[p][r + 8 + gid][tig + 4];
            al[mt][0] = As_l[p][r + gid][tig];
            al[mt][1] = As_l[p][r + 8 + gid][tig];
            al[mt][2] = As_l[p][r + gid][tig + 4];
            al[mt][3] = As_l[p][r + 8 + gid][tig + 4];
        }
        #pragma unroll
        for (int nt = 0; nt < 8; nt++) {
            int c = wn + nt * 8 + gid;
            uint32_t bh0 = Bs_h[p][c][tig], bh1 = Bs_h[p][c][tig + 4];
            uint32_t bl0 = Bs_l[p][c][tig], bl1 = Bs_l[p][c][tig + 4];
            #pragma unroll
            for (int mt = 0; mt < 2; mt++) {
                mma_bf16(acc[mt][nt], ah[mt][0], ah[mt][1], ah[mt][2], ah[mt][3], bh0, bh1);
                mma_bf16(acc[mt][nt], al[mt][0], al[mt][1], al[mt][2], al[mt][3], bh0, bh1);
                mma_bf16(acc[mt][nt], ah[mt][0], ah[mt][1], ah[mt][2], ah[mt][3], bl0, bl1);
            }
        }

        // ---- split + store next tile into alternate buffer
        if (kt + 1 < KT) {
            int q = 1 - p;
            #pragma unroll
            for (int it = 0; it < 4; it++) {
                int idx = tid + it * 256;
                int m   = idx >> 3;
                int kw  = idx & 7;
                uint32_t hi, lo;
                split2(aReg[it].x, aReg[it].y, hi, lo);
                As_h[q][m][kw] = hi;
                As_l[q][m][kw] = lo;
                int n   = idx & 127;
                int kwb = idx >> 7;
                split2(bReg[it].x, bReg[it].y, hi, lo);
                Bs_h[q][n][kwb] = hi;
                Bs_l[q][n][kwb] = lo;
            }
        }
        __syncthreads();
    }

    // ---- epilogue: bias + relu + store
    #pragma unroll
    for (int nt = 0; nt < 8; nt++) {
        int c = n0 + wn + nt * 8 + tig * 2;
        float bv0 = bias[c], bv1 = bias[c + 1];
        #pragma unroll
        for (int mt = 0; mt < 2; mt++) {
            int r0 = m0 + wm + mt * 16 + gid;
            int r1 = r0 + 8;
            float d0 = acc[mt][nt][0] + bv0;
            float d1 = acc[mt][nt][1] + bv1;
            float d2 = acc[mt][nt][2] + bv0;
            float d3 = acc[mt][nt][3] + bv1;
            if (RELU) {
                d0 = fmaxf(d0, 0.f); d1 = fmaxf(d1, 0.f);
                d2 = fmaxf(d2, 0.f); d3 = fmaxf(d3, 0.f);
            }
            if (r0 < N_NODES) *(float2*)(C + (size_t)r0 * N + c) = make_float2(d0, d1);
            if (r1 < N_NODES) *(float2*)(C + (size_t)r1 * N + c) = make_float2(d2, d3);
        }
    }
}

// ---------------- fp32 SIMT GEMM for readout (K=512 cat, N=40) ----------------
__global__ void __launch_bounds__(256)
readout_gemm_kernel(const float* __restrict__ B, const float* __restrict__ bias) {
    constexpr int K = 512, N = OUT_CH;
    float* C = bufptr<0>();

    __shared__ float As[16][128];
    __shared__ float Bs[16][64];
    int tid = threadIdx.x;
    int tx = tid & 15;
    int ty = tid >> 4;
    int m0 = blockIdx.y * 128;

    float acc[8][4];
    #pragma unroll
    for (int i = 0; i < 8; i++)
        #pragma unroll
        for (int j = 0; j < 4; j++) acc[i][j] = 0.f;

    for (int kt = 0; kt < K / 16; kt++) {
        #pragma unroll
        for (int l = 0; l < 2; l++) {
            int idx = tid + l * 256;
            int row = idx >> 2;
            int c4  = (idx & 3) * 4;
            int m = m0 + row;
            int kk = kt * 16 + c4;
            float4 v = make_float4(0.f, 0.f, 0.f, 0.f);
            if (m < N_NODES) {
                const float* srcp = (kk < 256)
                    ? ((const float*)g_h1 + (size_t)m * 256 + kk)
                    : ((const float*)g_h2 + (size_t)m * 256 + (kk - 256));
                v = *(const float4*)srcp;
            }
            As[c4 + 0][row] = v.x;
            As[c4 + 1][row] = v.y;
            As[c4 + 2][row] = v.z;
            As[c4 + 3][row] = v.w;
        }
        {
            int r  = tid >> 4;
            int c4 = (tid & 15) * 4;
            float4 v = make_float4(0.f, 0.f, 0.f, 0.f);
            if (c4 < N) v = *(const float4*)(B + (size_t)(kt * 16 + r) * N + c4);
            *(float4*)&Bs[r][c4] = v;
        }
        __syncthreads();

        #pragma unroll
        for (int k = 0; k < 16; k++) {
            float4 a0 = *(const float4*)&As[k][ty * 8];
            float4 a1 = *(const float4*)&As[k][ty * 8 + 4];
            float4 b  = *(const float4*)&Bs[k][tx * 4];
            float ar[8] = {a0.x, a0.y, a0.z, a0.w, a1.x, a1.y, a1.z, a1.w};
            float br[4] = {b.x, b.y, b.z, b.w};
            #pragma unroll
            for (int i = 0; i < 8; i++)
                #pragma unroll
                for (int j = 0; j < 4; j++)
                    acc[i][j] += ar[i] * br[j];
        }
        __syncthreads();
    }

    int colBase = tx * 4;
    float4 bv = make_float4(0.f, 0.f, 0.f, 0.f);
    if (colBase < N) bv = *(const float4*)(bias + colBase);
    #pragma unroll
    for (int i = 0; i < 8; i++) {
        int m = m0 + ty * 8 + i;
        if (m < N_NODES && colBase < N) {
            float4 o;
            o.x = acc[i][0] + bv.x;
            o.y = acc[i][1] + bv.y;
            o.z = acc[i][2] + bv.z;
            o.w = acc[i][3] + bv.w;
            *(float4*)(C + (size_t)m * N + colBase) = o;
        }
    }
}

// ---------------- log_softmax over 40 logits, one thread per node ----------------
__global__ void logsoftmax_kernel(float* __restrict__ out) {
    int n = blockIdx.x * blockDim.x + threadIdx.x;
    if (n >= N_NODES) return;
    const float* row = (const float*)g_z + (size_t)n * OUT_CH;
    float m = -3.0e38f;
    #pragma unroll
    for (int c = 0; c < OUT_CH; c++) m = fmaxf(m, row[c]);
    float s = 0.f;
    #pragma unroll
    for (int c = 0; c < OUT_CH; c++) s += expf(row[c] - m);
    float lse = m + logf(s);
    float* o = out + (size_t)n * OUT_CH;
    #pragma unroll
    for (int c = 0; c < OUT_CH; c++) o[c] = row[c] - lse;
}

// ---------------- launch ----------------
extern "C" void kernel_launch(void* const* d_in, const int* in_sizes, int n_in,
                              void* d_out, int out_size) {
    const float* x    = (const float*)d_in[0];
    const void*  ei   = (const void*)d_in[1];
    const float* W1a  = (const float*)d_in[2];
    const float* b1a  = (const float*)d_in[3];
    const float* W2a  = (const float*)d_in[4];
    const float* b2a  = (const float*)d_in[5];
    const float* W1b  = (const float*)d_in[6];
    const float* b1b  = (const float*)d_in[7];
    const float* W2b  = (const float*)d_in[8];
    const float* b2b  = (const float*)d_in[9];
    const float* Wlin = (const float*)d_in[10];
    const float* blin = (const float*)d_in[11];
    float* out = (float*)d_out;

    detect_kernel<<<1, 256>>>((const long long*)ei);

    dim3 mmaGrid(2, (N_NODES + 127) / 128);
    dim3 linGrid(1, (N_NODES + 127) / 128);
    int edgeBlocks = (N_EDGES * 32 + 255) / 256;

    // ---- layer 1
    copy_self_kernel<IN_CH, -1, 0><<<(N_NODES * IN_CH / 4 + 255) / 256, 256>>>(x);
    scatter_add_kernel<IN_CH, -1, 0><<<edgeBlocks, 256>>>(x, ei);
    mma_gemm_kernel<IN_CH, 0, 1, true><<<mmaGrid, 256>>>(W1a, b1a);
    mma_gemm_kernel<HID,   1, 2, true><<<mmaGrid, 256>>>(W2a, b2a);

    // ---- layer 2
    copy_self_kernel<HID, 2, 0><<<(N_NODES * HID / 4 + 255) / 256, 256>>>(nullptr);
    scatter_add_kernel<HID, 2, 0><<<edgeBlocks, 256>>>(nullptr, ei);
    mma_gemm_kernel<HID, 0, 1, true><<<mmaGrid, 256>>>(W1b, b1b);
    mma_gemm_kernel<HID, 1, 3, true><<<mmaGrid, 256>>>(W2b, b2b);

    // ---- readout + softmax
    readout_gemm_kernel<<<linGrid, 256>>>(Wlin, blin);
    logsoftmax_kernel<<<(N_NODES + 255) / 256, 256>>>(out);
}

// round 8
// speedup vs baseline: 1.4990x; 1.0081x over previous
#include <cuda_runtime.h>
#include <cuda_bf16.h>
#include <cstdint>

// ---------------- problem constants ----------------
#define N_NODES 50000
#define N_EDGES 800000
#define IN_CH   128
#define HID     256
#define OUT_CH  40

// ---------------- device scratch (no allocation anywhere) ----------------
__device__ float g_z [N_NODES * HID];   // z buffer (also reused for logits)
__device__ float g_t [N_NODES * HID];   // MLP intermediate
__device__ float g_h1[N_NODES * HID];
__device__ float g_h2[N_NODES * HID];
__device__ int   g_is32;                // edge_index element width flag

template <int S>
__device__ __forceinline__ float* bufptr() {
    if constexpr (S == 0) return g_z;
    else if constexpr (S == 1) return g_t;
    else if constexpr (S == 2) return g_h1;
    else return g_h2;
}

// ---------------- edge dtype probe ----------------
__global__ void detect_kernel(const long long* __restrict__ ei) {
    if (threadIdx.x == 0) g_is32 = 0;
    __syncthreads();
    long long v = ei[threadIdx.x];
    if (v < 0 || v >= N_NODES) atomicOr(&g_is32, 1);
}

__device__ __forceinline__ void load_edge(const void* eiv, int e, int& src, int& dst) {
    if (g_is32) {
        const int* p = (const int*)eiv;
        src = p[e];
        dst = p[N_EDGES + e];
    } else {
        const long long* p = (const long long*)eiv;
        src = (int)p[e];
        dst = (int)p[N_EDGES + e];
    }
}

// ---------------- z = h (self term) ----------------
template <int CH, int HSEL, int ZSEL>
__global__ void copy_self_kernel(const float* __restrict__ hp) {
    const float* h = (HSEL < 0) ? hp : (const float*)bufptr<HSEL>();
    float* z = bufptr<ZSEL>();
    size_t i = (size_t)blockIdx.x * blockDim.x + threadIdx.x;
    size_t total = (size_t)N_NODES * CH / 4;
    if (i < total) ((float4*)z)[i] = ((const float4*)h)[i];
}

// ---------------- z[dst] += h[src] over edges (one warp per edge) ----------------
// float4 hardware reductions (RED.128) — 4x fewer transactions than scalar.
template <int CH, int HSEL, int ZSEL>
__global__ void scatter_add_kernel(const float* __restrict__ hp,
                                   const void* __restrict__ eiv) {
    const float* h = (HSEL < 0) ? hp : (const float*)bufptr<HSEL>();
    float* z = bufptr<ZSEL>();
    int warp = (blockIdx.x * blockDim.x + threadIdx.x) >> 5;
    int lane = threadIdx.x & 31;
    if (warp >= N_EDGES) return;
    int src, dst;
    load_edge(eiv, warp, src, dst);
    const float4* hs = (const float4*)(h + (size_t)src * CH);
    float4* zd = (float4*)(z + (size_t)dst * CH);
    #pragma unroll
    for (int c = lane; c < CH / 4; c += 32) {
        float4 v = __ldg(hs + c);
        atomicAdd(zd + c, v);
    }
}

// ======================================================================
// Tensor-core GEMM: C[M,256] = act(A[M,K] @ B[K,256] + bias)
// bf16 3-term compensated split (A*B ~= Ah*Bh + Ah*Bl + Al*Bh).
// CTA tile 128x128, 8 warps of 32x64, BK=16, mma.sync m16n8k16.
// Double-buffered smem + register prefetch; one syncthreads per K-step.
// ======================================================================
__device__ __forceinline__ void mma_bf16(float* d, uint32_t a0, uint32_t a1,
                                         uint32_t a2, uint32_t a3,
                                         uint32_t b0, uint32_t b1) {
    asm volatile(
        "mma.sync.aligned.m16n8k16.row.col.f32.bf16.bf16.f32 "
        "{%0,%1,%2,%3}, {%4,%5,%6,%7}, {%8,%9}, {%0,%1,%2,%3};\n"
        : "+f"(d[0]), "+f"(d[1]), "+f"(d[2]), "+f"(d[3])
        : "r"(a0), "r"(a1), "r"(a2), "r"(a3), "r"(b0), "r"(b1));
}

__device__ __forceinline__ void split2(float a, float b, uint32_t& hi, uint32_t& lo) {
    __nv_bfloat16 ha = __float2bfloat16(a);
    __nv_bfloat16 hb = __float2bfloat16(b);
    __nv_bfloat16 la = __float2bfloat16(a - __bfloat162float(ha));
    __nv_bfloat16 lb = __float2bfloat16(b - __bfloat162float(hb));
    __nv_bfloat162 h2; h2.x = ha; h2.y = hb;
    __nv_bfloat162 l2; l2.x = la; l2.y = lb;
    hi = *(uint32_t*)&h2;
    lo = *(uint32_t*)&l2;
}

template <int K, int ASEL, int CSEL, bool RELU>
__global__ void __launch_bounds__(256, 2)
mma_gemm_kernel(const float* __restrict__ B, const float* __restrict__ bias) {
    constexpr int N = 256;
    constexpr int KT = K / 16;
    const float* A = bufptr<ASEL>();
    float* C = bufptr<CSEL>();

    // double-buffered smem tiles, bf16 pairs packed in u32; row stride 9 (pad)
    __shared__ uint32_t As_h[2][128][9], As_l[2][128][9];
    __shared__ uint32_t Bs_h[2][128][9], Bs_l[2][128][9];   // [n][k-pair]

    int tid  = threadIdx.x;
    int wid  = tid >> 5;
    int lane = tid & 31;
    int gid  = lane >> 2;   // group id 0..7
    int tig  = lane & 3;    // thread in group 0..3

    int m0 = blockIdx.y * 128;
    int n0 = blockIdx.x * 128;
    int wm = (wid & 3) * 32;   // warp row base
    int wn = (wid >> 2) * 64;  // warp col base

    // per-thread loader coordinates (fixed across K-steps)
    int aM  = tid >> 1;                 // covers rows tid/2 and tid/2 (2 slots/row? see below)
    // A tile: 128 rows x 8 u32-slots = 1024 pairs; thread handles 4 pairs:
    //   idx = tid + it*256 -> m = idx>>3, kw = idx&7
    // B tile: n = idx&127, kw = idx>>7
    (void)aM;

    float2 aReg[4];
    float2 bReg[4];

    // ---- prefetch tile 0 into registers
    {
        #pragma unroll
        for (int it = 0; it < 4; it++) {
            int idx = tid + it * 256;
            int m   = idx >> 3;
            int kw  = idx & 7;
            aReg[it] = make_float2(0.f, 0.f);
            if (m0 + m < N_NODES)
                aReg[it] = *(const float2*)(A + (size_t)(m0 + m) * K + kw * 2);
            int n    = idx & 127;
            int kwb  = idx >> 7;
            int krow = kwb * 2;
            bReg[it].x = __ldg(B + (size_t)krow * N + n0 + n);
            bReg[it].y = __ldg(B + (size_t)(krow + 1) * N + n0 + n);
        }
        // split + store buffer 0
        #pragma unroll
        for (int it = 0; it < 4; it++) {
            int idx = tid + it * 256;
            int m   = idx >> 3;
            int kw  = idx & 7;
            uint32_t hi, lo;
            split2(aReg[it].x, aReg[it].y, hi, lo);
            As_h[0][m][kw] = hi;
            As_l[0][m][kw] = lo;
            int n   = idx & 127;
            int kwb = idx >> 7;
            split2(bReg[it].x, bReg[it].y, hi, lo);
            Bs_h[0][n][kwb] = hi;
            Bs_l[0][n][kwb] = lo;
        }
    }
    __syncthreads();

    float acc[2][8][4];
    #pragma unroll
    for (int mt = 0; mt < 2; mt++)
        #pragma unroll
        for (int nt = 0; nt < 8; nt++)
            #pragma unroll
            for (int r = 0; r < 4; r++) acc[mt][nt][r] = 0.f;

    for (int kt = 0; kt < KT; kt++) {
        int p = kt & 1;
        // ---- issue global loads for next tile (latency hidden by MMA below)
        if (kt + 1 < KT) {
            #pragma unroll
            for (int it = 0; it < 4; it++) {
                int idx = tid + it * 256;
                int m   = idx >> 3;
                int kw  = idx & 7;
                aReg[it] = make_float2(0.f, 0.f);
                if (m0 + m < N_NODES)
                    aReg[it] = *(const float2*)(A + (size_t)(m0 + m) * K + (kt + 1) * 16 + kw * 2);
                int n    = idx & 127;
                int kwb  = idx >> 7;
                int krow = (kt + 1) * 16 + kwb * 2;
                bReg[it].x = __ldg(B + (size_t)krow * N + n0 + n);
                bReg[it].y = __ldg(B + (size_t)(krow + 1) * N + n0 + n);
            }
        }

        // ---- fragments + MMA on buffer p
        uint32_t ah[2][4], al[2][4];
        #pragma unroll
        for (int mt = 0; mt < 2; mt++) {
            int r = wm + mt * 16;
            ah[mt][0] = As_h[p][r + gid][tig];
            ah[mt][1] = As_h[p][r + 8 + gid][tig];
            ah[mt][2] = As_h[p][r + gid][tig + 4];
            ah[mt][3] = As_h[p][r + 8 + gid][tig + 4];
            al[mt][0] = As_l[p][r + gid][tig];
            al[mt][1] = As_l[p][r + 8 + gid][tig];
            al[mt][2] = As_l[p][r + gid][tig + 4];
            al[mt][3] = As_l[p][r + 8 + gid][tig + 4];
        }
        #pragma unroll
        for (int nt = 0; nt < 8; nt++) {
            int c = wn + nt * 8 + gid;
            uint32_t bh0 = Bs_h[p][c][tig], bh1 = Bs_h[p][c][tig + 4];
            uint32_t bl0 = Bs_l[p][c][tig], bl1 = Bs_l[p][c][tig + 4];
            #pragma unroll
            for (int mt = 0; mt < 2; mt++) {
                mma_bf16(acc[mt][nt], ah[mt][0], ah[mt][1], ah[mt][2], ah[mt][3], bh0, bh1);
                mma_bf16(acc[mt][nt], al[mt][0], al[mt][1], al[mt][2], al[mt][3], bh0, bh1);
                mma_bf16(acc[mt][nt], ah[mt][0], ah[mt][1], ah[mt][2], ah[mt][3], bl0, bl1);
            }
        }

        // ---- split + store next tile into alternate buffer
        if (kt + 1 < KT) {
            int q = 1 - p;
            #pragma unroll
            for (int it = 0; it < 4; it++) {
                int idx = tid + it * 256;
                int m   = idx >> 3;
                int kw  = idx & 7;
                uint32_t hi, lo;
                split2(aReg[it].x, aReg[it].y, hi, lo);
                As_h[q][m][kw] = hi;
                As_l[q][m][kw] = lo;
                int n   = idx & 127;
                int kwb = idx >> 7;
                split2(bReg[it].x, bReg[it].y, hi, lo);
                Bs_h[q][n][kwb] = hi;
                Bs_l[q][n][kwb] = lo;
            }
        }
        __syncthreads();
    }

    // ---- epilogue: bias + relu + store
    #pragma unroll
    for (int nt = 0; nt < 8; nt++) {
        int c = n0 + wn + nt * 8 + tig * 2;
        float bv0 = bias[c], bv1 = bias[c + 1];
        #pragma unroll
        for (int mt = 0; mt < 2; mt++) {
            int r0 = m0 + wm + mt * 16 + gid;
            int r1 = r0 + 8;
            float d0 = acc[mt][nt][0] + bv0;
            float d1 = acc[mt][nt][1] + bv1;
            float d2 = acc[mt][nt][2] + bv0;
            float d3 = acc[mt][nt][3] + bv1;
            if (RELU) {
                d0 = fmaxf(d0, 0.f); d1 = fmaxf(d1, 0.f);
                d2 = fmaxf(d2, 0.f); d3 = fmaxf(d3, 0.f);
            }
            if (r0 < N_NODES) *(float2*)(C + (size_t)r0 * N + c) = make_float2(d0, d1);
            if (r1 < N_NODES) *(float2*)(C + (size_t)r1 * N + c) = make_float2(d2, d3);
        }
    }
}

// ---------------- fp32 SIMT GEMM for readout (K=512 cat, N=40) ----------------
__global__ void __launch_bounds__(256)
readout_gemm_kernel(const float* __restrict__ B, const float* __restrict__ bias) {
    constexpr int K = 512, N = OUT_CH;
    float* C = bufptr<0>();

    __shared__ float As[16][128];
    __shared__ float Bs[16][64];
    int tid = threadIdx.x;
    int tx = tid & 15;
    int ty = tid >> 4;
    int m0 = blockIdx.y * 128;

    float acc[8][4];
    #pragma unroll
    for (int i = 0; i < 8; i++)
        #pragma unroll
        for (int j = 0; j < 4; j++) acc[i][j] = 0.f;

    for (int kt = 0; kt < K / 16; kt++) {
        #pragma unroll
        for (int l = 0; l < 2; l++) {
            int idx = tid + l * 256;
            int row = idx >> 2;
            int c4  = (idx & 3) * 4;
            int m = m0 + row;
            int kk = kt * 16 + c4;
            float4 v = make_float4(0.f, 0.f, 0.f, 0.f);
            if (m < N_NODES) {
                const float* srcp = (kk < 256)
                    ? ((const float*)g_h1 + (size_t)m * 256 + kk)
                    : ((const float*)g_h2 + (size_t)m * 256 + (kk - 256));
                v = *(const float4*)srcp;
            }
            As[c4 + 0][row] = v.x;
            As[c4 + 1][row] = v.y;
            As[c4 + 2][row] = v.z;
            As[c4 + 3][row] = v.w;
        }
        {
            int r  = tid >> 4;
            int c4 = (tid & 15) * 4;
            float4 v = make_float4(0.f, 0.f, 0.f, 0.f);
            if (c4 < N) v = *(const float4*)(B + (size_t)(kt * 16 + r) * N + c4);
            *(float4*)&Bs[r][c4] = v;
        }
        __syncthreads();

        #pragma unroll
        for (int k = 0; k < 16; k++) {
            float4 a0 = *(const float4*)&As[k][ty * 8];
            float4 a1 = *(const float4*)&As[k][ty * 8 + 4];
            float4 b  = *(const float4*)&Bs[k][tx * 4];
            float ar[8] = {a0.x, a0.y, a0.z, a0.w, a1.x, a1.y, a1.z, a1.w};
            float br[4] = {b.x, b.y, b.z, b.w};
            #pragma unroll
            for (int i = 0; i < 8; i++)
                #pragma unroll
                for (int j = 0; j < 4; j++)
                    acc[i][j] += ar[i] * br[j];
        }
        __syncthreads();
    }

    int colBase = tx * 4;
    float4 bv = make_float4(0.f, 0.f, 0.f, 0.f);
    if (colBase < N) bv = *(const float4*)(bias + colBase);
    #pragma unroll
    for (int i = 0; i < 8; i++) {
        int m = m0 + ty * 8 + i;
        if (m < N_NODES && colBase < N) {
            float4 o;
            o.x = acc[i][0] + bv.x;
            o.y = acc[i][1] + bv.y;
            o.z = acc[i][2] + bv.z;
            o.w = acc[i][3] + bv.w;
            *(float4*)(C + (size_t)m * N + colBase) = o;
        }
    }
}

// ---------------- log_softmax over 40 logits, one thread per node ----------------
__global__ void logsoftmax_kernel(float* __restrict__ out) {
    int n = blockIdx.x * blockDim.x + threadIdx.x;
    if (n >= N_NODES) return;
    const float* row = (const float*)g_z + (size_t)n * OUT_CH;
    float m = -3.0e38f;
    #pragma unroll
    for (int c = 0; c < OUT_CH; c++) m = fmaxf(m, row[c]);
    float s = 0.f;
    #pragma unroll
    for (int c = 0; c < OUT_CH; c++) s += expf(row[c] - m);
    float lse = m + logf(s);
    float* o = out + (size_t)n * OUT_CH;
    #pragma unroll
    for (int c = 0; c < OUT_CH; c++) o[c] = row[c] - lse;
}

// ---------------- launch ----------------
extern "C" void kernel_launch(void* const* d_in, const int* in_sizes, int n_in,
                              void* d_out, int out_size) {
    const float* x    = (const float*)d_in[0];
    const void*  ei   = (const void*)d_in[1];
    const float* W1a  = (const float*)d_in[2];
    const float* b1a  = (const float*)d_in[3];
    const float* W2a  = (const float*)d_in[4];
    const float* b2a  = (const float*)d_in[5];
    const float* W1b  = (const float*)d_in[6];
    const float* b1b  = (const float*)d_in[7];
    const float* W2b  = (const float*)d_in[8];
    const float* b2b  = (const float*)d_in[9];
    const float* Wlin = (const float*)d_in[10];
    const float* blin = (const float*)d_in[11];
    float* out = (float*)d_out;

    detect_kernel<<<1, 256>>>((const long long*)ei);

    dim3 mmaGrid(2, (N_NODES + 127) / 128);
    dim3 linGrid(1, (N_NODES + 127) / 128);
    int edgeBlocks = (N_EDGES * 32 + 255) / 256;

    // ---- layer 1
    copy_self_kernel<IN_CH, -1, 0><<<(N_NODES * IN_CH / 4 + 255) / 256, 256>>>(x);
    scatter_add_kernel<IN_CH, -1, 0><<<edgeBlocks, 256>>>(x, ei);
    mma_gemm_kernel<IN_CH, 0, 1, true><<<mmaGrid, 256>>>(W1a, b1a);
    mma_gemm_kernel<HID,   1, 2, true><<<mmaGrid, 256>>>(W2a, b2a);

    // ---- layer 2
    copy_self_kernel<HID, 2, 0><<<(N_NODES * HID / 4 + 255) / 256, 256>>>(nullptr);
    scatter_add_kernel<HID, 2, 0><<<edgeBlocks, 256>>>(nullptr, ei);
    mma_gemm_kernel<HID, 0, 1, true><<<mmaGrid, 256>>>(W1b, b1b);
    mma_gemm_kernel<HID, 1, 3, true><<<mmaGrid, 256>>>(W2b, b2b);

    // ---- readout + softmax
    readout_gemm_kernel<<<linGrid, 256>>>(Wlin, blin);
    logsoftmax_kernel<<<(N_NODES + 255) / 256, 256>>>(out);
}

// round 10
// speedup vs baseline: 1.7955x; 1.1978x over previous
#include <cuda_runtime.h>
#include <cuda_bf16.h>
#include <cstdint>

// ---------------- problem constants ----------------
#define N_NODES 50000
#define N_EDGES 800000
#define IN_CH   128
#define HID     256
#define OUT_CH  40

// ---------------- device scratch (no allocation anywhere) ----------------
__device__ float g_z [N_NODES * HID];
__device__ float g_t [N_NODES * HID];
__device__ float g_h1[N_NODES * HID];
__device__ float g_h2[N_NODES * HID];
__device__ int   g_is32;
__device__ int   g_deg[N_NODES];
__device__ int   g_off[N_NODES + 1];
__device__ int   g_pos[N_NODES];
__device__ int   g_col[N_EDGES];

template <int S>
__device__ __forceinline__ float* bufptr() {
    if constexpr (S == 0) return g_z;
    else if constexpr (S == 1) return g_t;
    else if constexpr (S == 2) return g_h1;
    else return g_h2;
}

// ---------------- edge dtype probe ----------------
// int64 view of an int32 buffer packs two random indices -> >= 2^32 a.s.
__global__ void detect_kernel(const long long* __restrict__ ei) {
    if (threadIdx.x == 0) g_is32 = 0;
    __syncthreads();
    long long v = ei[threadIdx.x];
    if (v < 0 || v >= N_NODES) atomicOr(&g_is32, 1);
}

// ALWAYS use this for edge reads (raw int64 reads on an int32 buffer caused
// the wild-atomic 717 trap in early rounds).
__device__ __forceinline__ void load_edge(const void* eiv, int e, int& src, int& dst) {
    if (g_is32) {
        const int* p = (const int*)eiv;
        src = p[e];
        dst = p[N_EDGES + e];
    } else {
        const long long* p = (const long long*)eiv;
        src = (int)p[e];
        dst = (int)p[N_EDGES + e];
    }
}

__device__ __forceinline__ int load_dst(const void* eiv, int e) {
    if (g_is32) return ((const int*)eiv)[N_EDGES + e];
    return (int)((const long long*)eiv)[N_EDGES + e];
}

// ---------------- CSR build ----------------
__global__ void zero_deg_kernel() {
    int i = blockIdx.x * blockDim.x + threadIdx.x;
    if (i < N_NODES) g_deg[i] = 0;
}

__global__ void hist_kernel(const void* __restrict__ ei) {
    int e = blockIdx.x * blockDim.x + threadIdx.x;
    if (e < N_EDGES) {
        int dst = load_dst(ei, e);
        atomicAdd(&g_deg[dst], 1);
    }
}

// single-block exclusive scan over g_deg -> g_off (and g_pos copy)
__global__ void scan_kernel() {
    __shared__ int wsum[32];
    __shared__ int s_carry;
    if (threadIdx.x == 0) s_carry = 0;
    __syncthreads();
    int lane = threadIdx.x & 31, wid = threadIdx.x >> 5;
    for (int base = 0; base < N_NODES; base += 1024) {
        int i = base + threadIdx.x;
        int v = (i < N_NODES) ? g_deg[i] : 0;
        int x = v;
        #pragma unroll
        for (int d = 1; d < 32; d <<= 1) {
            int y = __shfl_up_sync(0xffffffffu, x, d);
            if (lane >= d) x += y;
        }
        if (lane == 31) wsum[wid] = x;
        __syncthreads();
        if (wid == 0) {
            int w = wsum[lane];
            #pragma unroll
            for (int d = 1; d < 32; d <<= 1) {
                int y = __shfl_up_sync(0xffffffffu, w, d);
                if (lane >= d) w += y;
            }
            wsum[lane] = w;
        }
        __syncthreads();
        int excl = x - v + (wid > 0 ? wsum[wid - 1] : 0);
        int carry = s_carry;
        if (i < N_NODES) {
            int o = carry + excl;
            g_off[i] = o;
            g_pos[i] = o;
        }
        __syncthreads();
        if (threadIdx.x == 0) s_carry = carry + wsum[31];
        __syncthreads();
    }
    if (threadIdx.x == 0) g_off[N_NODES] = s_carry;
}

__global__ void csr_scatter_kernel(const void* __restrict__ ei) {
    int e = blockIdx.x * blockDim.x + threadIdx.x;
    if (e < N_EDGES) {
        int src, dst;
        load_edge(ei, e, src, dst);
        int p = atomicAdd(&g_pos[dst], 1);
        g_col[p] = src;
    }
}

// ---------------- aggregation: z[n] = h[n] + sum_{s in N(n)} h[s] ----------------
// one warp per destination node via CSR gather (atomic-free, fuses self term)
template <int CH, int HSEL, int ZSEL>
__global__ void agg_kernel(const float* __restrict__ hp) {
    const float* h = (HSEL < 0) ? hp : (const float*)bufptr<HSEL>();
    float* z = bufptr<ZSEL>();
    int warp = (blockIdx.x * blockDim.x + threadIdx.x) >> 5;
    int lane = threadIdx.x & 31;
    if (warp >= N_NODES) return;
    constexpr int V = CH / 128;  // float4 per lane
    float4 acc[V];
    #pragma unroll
    for (int v = 0; v < V; v++)
        acc[v] = __ldg((const float4*)(h + (size_t)warp * CH + v * 128 + lane * 4));
    int s = g_off[warp], e = g_off[warp + 1];
    for (int i = s; i < e; i++) {
        int c = g_col[i];
        const float* row = h + (size_t)c * CH;
        #pragma unroll
        for (int v = 0; v < V; v++) {
            float4 t = __ldg((const float4*)(row + v * 128 + lane * 4));
            acc[v].x += t.x; acc[v].y += t.y; acc[v].z += t.z; acc[v].w += t.w;
        }
    }
    #pragma unroll
    for (int v = 0; v < V; v++)
        *(float4*)(z + (size_t)warp * CH + v * 128 + lane * 4) = acc[v];
}

// ======================================================================
// Tensor-core GEMM: C[M,256] = act(A[M,K] @ B[K,256] + bias)
// bf16 3-term compensated split (A*B ~= Ah*Bh + Ah*Bl + Al*Bh).
// CTA tile 128x128, 8 warps of 32x64, BK=16, mma.sync m16n8k16.
// Double-buffered smem + register prefetch; one syncthreads per K-step.
// ======================================================================
__device__ __forceinline__ void mma_bf16(float* d, uint32_t a0, uint32_t a1,
                                         uint32_t a2, uint32_t a3,
                                         uint32_t b0, uint32_t b1) {
    asm volatile(
        "mma.sync.aligned.m16n8k16.row.col.f32.bf16.bf16.f32 "
        "{%0,%1,%2,%3}, {%4,%5,%6,%7}, {%8,%9}, {%0,%1,%2,%3};\n"
        : "+f"(d[0]), "+f"(d[1]), "+f"(d[2]), "+f"(d[3])
        : "r"(a0), "r"(a1), "r"(a2), "r"(a3), "r"(b0), "r"(b1));
}

__device__ __forceinline__ void split2(float a, float b, uint32_t& hi, uint32_t& lo) {
    __nv_bfloat16 ha = __float2bfloat16(a);
    __nv_bfloat16 hb = __float2bfloat16(b);
    __nv_bfloat16 la = __float2bfloat16(a - __bfloat162float(ha));
    __nv_bfloat16 lb = __float2bfloat16(b - __bfloat162float(hb));
    __nv_bfloat162 h2; h2.x = ha; h2.y = hb;
    __nv_bfloat162 l2; l2.x = la; l2.y = lb;
    hi = *(uint32_t*)&h2;
    lo = *(uint32_t*)&l2;
}

template <int K, int ASEL, int CSEL, bool RELU>
__global__ void __launch_bounds__(256, 2)
mma_gemm_kernel(const float* __restrict__ B, const float* __restrict__ bias) {
    constexpr int N = 256;
    constexpr int KT = K / 16;
    const float* A = bufptr<ASEL>();
    float* C = bufptr<CSEL>();

    __shared__ uint32_t As_h[2][128][9], As_l[2][128][9];
    __shared__ uint32_t Bs_h[2][128][9], Bs_l[2][128][9];   // [n][k-pair]

    int tid  = threadIdx.x;
    int wid  = tid >> 5;
    int lane = tid & 31;
    int gid  = lane >> 2;
    int tig  = lane & 3;

    int m0 = blockIdx.y * 128;
    int n0 = blockIdx.x * 128;
    int wm = (wid & 3) * 32;
    int wn = (wid >> 2) * 64;

    float2 aReg[4];
    float2 bReg[4];

    // ---- prefetch tile 0
    {
        #pragma unroll
        for (int it = 0; it < 4; it++) {
            int idx = tid + it * 256;
            int m   = idx >> 3;
            int kw  = idx & 7;
            aReg[it] = make_float2(0.f, 0.f);
            if (m0 + m < N_NODES)
                aReg[it] = *(const float2*)(A + (size_t)(m0 + m) * K + kw * 2);
            int n    = idx & 127;
            int kwb  = idx >> 7;
            int krow = kwb * 2;
            bReg[it].x = __ldg(B + (size_t)krow * N + n0 + n);
            bReg[it].y = __ldg(B + (size_t)(krow + 1) * N + n0 + n);
        }
        #pragma unroll
        for (int it = 0; it < 4; it++) {
            int idx = tid + it * 256;
            int m   = idx >> 3;
            int kw  = idx & 7;
            uint32_t hi, lo;
            split2(aReg[it].x, aReg[it].y, hi, lo);
            As_h[0][m][kw] = hi;
            As_l[0][m][kw] = lo;
            int n   = idx & 127;
            int kwb = idx >> 7;
            split2(bReg[it].x, bReg[it].y, hi, lo);
            Bs_h[0][n][kwb] = hi;
            Bs_l[0][n][kwb] = lo;
        }
    }
    __syncthreads();

    float acc[2][8][4];
    #pragma unroll
    for (int mt = 0; mt < 2; mt++)
        #pragma unroll
        for (int nt = 0; nt < 8; nt++)
            #pragma unroll
            for (int r = 0; r < 4; r++) acc[mt][nt][r] = 0.f;

    for (int kt = 0; kt < KT; kt++) {
        int p = kt & 1;
        if (kt + 1 < KT) {
            #pragma unroll
            for (int it = 0; it < 4; it++) {
                int idx = tid + it * 256;
                int m   = idx >> 3;
                int kw  = idx & 7;
                aReg[it] = make_float2(0.f, 0.f);
                if (m0 + m < N_NODES)
                    aReg[it] = *(const float2*)(A + (size_t)(m0 + m) * K + (kt + 1) * 16 + kw * 2);
                int n    = idx & 127;
                int kwb  = idx >> 7;
                int krow = (kt + 1) * 16 + kwb * 2;
                bReg[it].x = __ldg(B + (size_t)krow * N + n0 + n);
                bReg[it].y = __ldg(B + (size_t)(krow + 1) * N + n0 + n);
            }
        }

        uint32_t ah[2][4], al[2][4];
        #pragma unroll
        for (int mt = 0; mt < 2; mt++) {
            int r = wm + mt * 16;
            ah[mt][0] = As_h[p][r + gid][tig];
            ah[mt][1] = As_h[p][r + 8 + gid][tig];
            ah[mt][2] = As_h[p][r + gid][tig + 4];
            ah[mt][3] = As_h[p][r + 8 + gid][tig + 4];
            al[mt][0] = As_l[p][r + gid][tig];
            al[mt][1] = As_l[p][r + 8 + gid][tig];
            al[mt][2] = As_l[p][r + gid][tig + 4];
            al[mt][3] = As_l[p][r + 8 + gid][tig + 4];
        }
        #pragma unroll
        for (int nt = 0; nt < 8; nt++) {
            int c = wn + nt * 8 + gid;
            uint32_t bh0 = Bs_h[p][c][tig], bh1 = Bs_h[p][c][tig + 4];
            uint32_t bl0 = Bs_l[p][c][tig], bl1 = Bs_l[p][c][tig + 4];
            #pragma unroll
            for (int mt = 0; mt < 2; mt++) {
                mma_bf16(acc[mt][nt], ah[mt][0], ah[mt][1], ah[mt][2], ah[mt][3], bh0, bh1);
                mma_bf16(acc[mt][nt], al[mt][0], al[mt][1], al[mt][2], al[mt][3], bh0, bh1);
                mma_bf16(acc[mt][nt], ah[mt][0], ah[mt][1], ah[mt][2], ah[mt][3], bl0, bl1);
            }
        }

        if (kt + 1 < KT) {
            int q = 1 - p;
            #pragma unroll
            for (int it = 0; it < 4; it++) {
                int idx = tid + it * 256;
                int m   = idx >> 3;
                int kw  = idx & 7;
                uint32_t hi, lo;
                split2(aReg[it].x, aReg[it].y, hi, lo);
                As_h[q][m][kw] = hi;
                As_l[q][m][kw] = lo;
                int n   = idx & 127;
                int kwb = idx >> 7;
                split2(bReg[it].x, bReg[it].y, hi, lo);
                Bs_h[q][n][kwb] = hi;
                Bs_l[q][n][kwb] = lo;
            }
        }
        __syncthreads();
    }

    #pragma unroll
    for (int nt = 0; nt < 8; nt++) {
        int c = n0 + wn + nt * 8 + tig * 2;
        float bv0 = bias[c], bv1 = bias[c + 1];
        #pragma unroll
        for (int mt = 0; mt < 2; mt++) {
            int r0 = m0 + wm + mt * 16 + gid;
            int r1 = r0 + 8;
            float d0 = acc[mt][nt][0] + bv0;
            float d1 = acc[mt][nt][1] + bv1;
            float d2 = acc[mt][nt][2] + bv0;
            float d3 = acc[mt][nt][3] + bv1;
            if (RELU) {
                d0 = fmaxf(d0, 0.f); d1 = fmaxf(d1, 0.f);
                d2 = fmaxf(d2, 0.f); d3 = fmaxf(d3, 0.f);
            }
            if (r0 < N_NODES) *(float2*)(C + (size_t)r0 * N + c) = make_float2(d0, d1);
            if (r1 < N_NODES) *(float2*)(C + (size_t)r1 * N + c) = make_float2(d2, d3);
        }
    }
}

// ---------------- fp32 SIMT GEMM for readout (K=512 cat, N=40) ----------------
__global__ void __launch_bounds__(256)
readout_gemm_kernel(const float* __restrict__ B, const float* __restrict__ bias) {
    constexpr int K = 512, N = OUT_CH;
    float* C = bufptr<0>();

    __shared__ float As[16][128];
    __shared__ float Bs[16][64];
    int tid = threadIdx.x;
    int tx = tid & 15;
    int ty = tid >> 4;
    int m0 = blockIdx.y * 128;

    float acc[8][4];
    #pragma unroll
    for (int i = 0; i < 8; i++)
        #pragma unroll
        for (int j = 0; j < 4; j++) acc[i][j] = 0.f;

    for (int kt = 0; kt < K / 16; kt++) {
        #pragma unroll
        for (int l = 0; l < 2; l++) {
            int idx = tid + l * 256;
            int row = idx >> 2;
            int c4  = (idx & 3) * 4;
            int m = m0 + row;
            int kk = kt * 16 + c4;
            float4 v = make_float4(0.f, 0.f, 0.f, 0.f);
            if (m < N_NODES) {
                const float* srcp = (kk < 256)
                    ? ((const float*)g_h1 + (size_t)m * 256 + kk)
                    : ((const float*)g_h2 + (size_t)m * 256 + (kk - 256));
                v = *(const float4*)srcp;
            }
            As[c4 + 0][row] = v.x;
            As[c4 + 1][row] = v.y;
            As[c4 + 2][row] = v.z;
            As[c4 + 3][row] = v.w;
        }
        {
            int r  = tid >> 4;
            int c4 = (tid & 15) * 4;
            float4 v = make_float4(0.f, 0.f, 0.f, 0.f);
            if (c4 < N) v = *(const float4*)(B + (size_t)(kt * 16 + r) * N + c4);
            *(float4*)&Bs[r][c4] = v;
        }
        __syncthreads();

        #pragma unroll
        for (int k = 0; k < 16; k++) {
            float4 a0 = *(const float4*)&As[k][ty * 8];
            float4 a1 = *(const float4*)&As[k][ty * 8 + 4];
            float4 b  = *(const float4*)&Bs[k][tx * 4];
            float ar[8] = {a0.x, a0.y, a0.z, a0.w, a1.x, a1.y, a1.z, a1.w};
            float br[4] = {b.x, b.y, b.z, b.w};
            #pragma unroll
            for (int i = 0; i < 8; i++)
                #pragma unroll
                for (int j = 0; j < 4; j++)
                    acc[i][j] += ar[i] * br[j];
        }
        __syncthreads();
    }

    int colBase = tx * 4;
    float4 bv = make_float4(0.f, 0.f, 0.f, 0.f);
    if (colBase < N) bv = *(const float4*)(bias + colBase);
    #pragma unroll
    for (int i = 0; i < 8; i++) {
        int m = m0 + ty * 8 + i;
        if (m < N_NODES && colBase < N) {
            float4 o;
            o.x = acc[i][0] + bv.x;
            o.y = acc[i][1] + bv.y;
            o.z = acc[i][2] + bv.z;
            o.w = acc[i][3] + bv.w;
            *(float4*)(C + (size_t)m * N + colBase) = o;
        }
    }
}

// ---------------- log_softmax over 40 logits, one thread per node ----------------
__global__ void logsoftmax_kernel(float* __restrict__ out) {
    int n = blockIdx.x * blockDim.x + threadIdx.x;
    if (n >= N_NODES) return;
    const float* row = (const float*)g_z + (size_t)n * OUT_CH;
    float m = -3.0e38f;
    #pragma unroll
    for (int c = 0; c < OUT_CH; c++) m = fmaxf(m, row[c]);
    float s = 0.f;
    #pragma unroll
    for (int c = 0; c < OUT_CH; c++) s += expf(row[c] - m);
    float lse = m + logf(s);
    float* o = out + (size_t)n * OUT_CH;
    #pragma unroll
    for (int c = 0; c < OUT_CH; c++) o[c] = row[c] - lse;
}

// ---------------- launch ----------------
extern "C" void kernel_launch(void* const* d_in, const int* in_sizes, int n_in,
                              void* d_out, int out_size) {
    const float* x    = (const float*)d_in[0];
    const void*  ei   = (const void*)d_in[1];
    const float* W1a  = (const float*)d_in[2];
    const float* b1a  = (const float*)d_in[3];
    const float* W2a  = (const float*)d_in[4];
    const float* b2a  = (const float*)d_in[5];
    const float* W1b  = (const float*)d_in[6];
    const float* b1b  = (const float*)d_in[7];
    const float* W2b  = (const float*)d_in[8];
    const float* b2b  = (const float*)d_in[9];
    const float* Wlin = (const float*)d_in[10];
    const float* blin = (const float*)d_in[11];
    float* out = (float*)d_out;

    detect_kernel<<<1, 256>>>((const long long*)ei);

    // CSR build (int atomics only; all edge reads go through load_edge)
    zero_deg_kernel<<<(N_NODES + 255) / 256, 256>>>();
    hist_kernel<<<(N_EDGES + 255) / 256, 256>>>(ei);
    scan_kernel<<<1, 1024>>>();
    csr_scatter_kernel<<<(N_EDGES + 255) / 256, 256>>>(ei);

    dim3 mmaGrid(2, (N_NODES + 127) / 128);
    dim3 linGrid(1, (N_NODES + 127) / 128);
    int aggBlocks = (N_NODES + 7) / 8;   // 8 warps/block, warp per node

    // ---- layer 1
    agg_kernel<IN_CH, -1, 0><<<aggBlocks, 256>>>(x);
    mma_gemm_kernel<IN_CH, 0, 1, true><<<mmaGrid, 256>>>(W1a, b1a);
    mma_gemm_kernel<HID,   1, 2, true><<<mmaGrid, 256>>>(W2a, b2a);

    // ---- layer 2
    agg_kernel<HID, 2, 0><<<aggBlocks, 256>>>(nullptr);
    mma_gemm_kernel<HID, 0, 1, true><<<mmaGrid, 256>>>(W1b, b1b);
    mma_gemm_kernel<HID, 1, 3, true><<<mmaGrid, 256>>>(W2b, b2b);

    // ---- readout + softmax
    readout_gemm_kernel<<<linGrid, 256>>>(Wlin, blin);
    logsoftmax_kernel<<<(N_NODES + 255) / 256, 256>>>(out);
}

// round 11
// speedup vs baseline: 1.7971x; 1.0009x over previous
#include <cuda_runtime.h>
#include <cuda_bf16.h>
#include <cstdint>

// ---------------- problem constants ----------------
#define N_NODES 50000
#define N_EDGES 800000
#define IN_CH   128
#define HID     256
#define OUT_CH  40

// ---------------- device scratch (no allocation anywhere) ----------------
__device__ float g_z [N_NODES * HID];
__device__ float g_t [N_NODES * HID];
__device__ float g_h1[N_NODES * HID];
__device__ float g_h2[N_NODES * HID];
__device__ int   g_is32;
__device__ int   g_deg[N_NODES];
__device__ int   g_off[N_NODES + 1];
__device__ int   g_pos[N_NODES];
__device__ int   g_col[N_EDGES];

template <int S>
__device__ __forceinline__ float* bufptr() {
    if constexpr (S == 0) return g_z;
    else if constexpr (S == 1) return g_t;
    else if constexpr (S == 2) return g_h1;
    else return g_h2;
}

// ---------------- edge dtype probe ----------------
// int64 view of an int32 buffer packs two random indices -> >= 2^32 a.s.
__global__ void detect_kernel(const long long* __restrict__ ei) {
    if (threadIdx.x == 0) g_is32 = 0;
    __syncthreads();
    long long v = ei[threadIdx.x];
    if (v < 0 || v >= N_NODES) atomicOr(&g_is32, 1);
}

// ALWAYS use this for edge reads (raw int64 reads on an int32 buffer caused
// the wild-atomic 717 trap in early rounds).
__device__ __forceinline__ void load_edge(const void* eiv, int e, int& src, int& dst) {
    if (g_is32) {
        const int* p = (const int*)eiv;
        src = p[e];
        dst = p[N_EDGES + e];
    } else {
        const long long* p = (const long long*)eiv;
        src = (int)p[e];
        dst = (int)p[N_EDGES + e];
    }
}

__device__ __forceinline__ int load_dst(const void* eiv, int e) {
    if (g_is32) return ((const int*)eiv)[N_EDGES + e];
    return (int)((const long long*)eiv)[N_EDGES + e];
}

// ---------------- CSR build ----------------
__global__ void zero_deg_kernel() {
    int i = blockIdx.x * blockDim.x + threadIdx.x;
    if (i < N_NODES) g_deg[i] = 0;
}

__global__ void hist_kernel(const void* __restrict__ ei) {
    int e = blockIdx.x * blockDim.x + threadIdx.x;
    if (e < N_EDGES) {
        int dst = load_dst(ei, e);
        atomicAdd(&g_deg[dst], 1);
    }
}

// single-block exclusive scan over g_deg -> g_off (and g_pos copy)
__global__ void scan_kernel() {
    __shared__ int wsum[32];
    __shared__ int s_carry;
    if (threadIdx.x == 0) s_carry = 0;
    __syncthreads();
    int lane = threadIdx.x & 31, wid = threadIdx.x >> 5;
    for (int base = 0; base < N_NODES; base += 1024) {
        int i = base + threadIdx.x;
        int v = (i < N_NODES) ? g_deg[i] : 0;
        int x = v;
        #pragma unroll
        for (int d = 1; d < 32; d <<= 1) {
            int y = __shfl_up_sync(0xffffffffu, x, d);
            if (lane >= d) x += y;
        }
        if (lane == 31) wsum[wid] = x;
        __syncthreads();
        if (wid == 0) {
            int w = wsum[lane];
            #pragma unroll
            for (int d = 1; d < 32; d <<= 1) {
                int y = __shfl_up_sync(0xffffffffu, w, d);
                if (lane >= d) w += y;
            }
            wsum[lane] = w;
        }
        __syncthreads();
        int excl = x - v + (wid > 0 ? wsum[wid - 1] : 0);
        int carry = s_carry;
        if (i < N_NODES) {
            int o = carry + excl;
            g_off[i] = o;
            g_pos[i] = o;
        }
        __syncthreads();
        if (threadIdx.x == 0) s_carry = carry + wsum[31];
        __syncthreads();
    }
    if (threadIdx.x == 0) g_off[N_NODES] = s_carry;
}

__global__ void csr_scatter_kernel(const void* __restrict__ ei) {
    int e = blockIdx.x * blockDim.x + threadIdx.x;
    if (e < N_EDGES) {
        int src, dst;
        load_edge(ei, e, src, dst);
        int p = atomicAdd(&g_pos[dst], 1);
        g_col[p] = src;
    }
}

// ---------------- aggregation: z[n] = h[n] + sum_{s in N(n)} h[s] ----------------
// one warp per destination node via CSR gather (atomic-free, fuses self term)
template <int CH, int HSEL, int ZSEL>
__global__ void agg_kernel(const float* __restrict__ hp) {
    const float* h = (HSEL < 0) ? hp : (const float*)bufptr<HSEL>();
    float* z = bufptr<ZSEL>();
    int warp = (blockIdx.x * blockDim.x + threadIdx.x) >> 5;
    int lane = threadIdx.x & 31;
    if (warp >= N_NODES) return;
    constexpr int V = CH / 128;  // float4 per lane
    float4 acc[V];
    #pragma unroll
    for (int v = 0; v < V; v++)
        acc[v] = __ldg((const float4*)(h + (size_t)warp * CH + v * 128 + lane * 4));
    int s = g_off[warp], e = g_off[warp + 1];
    for (int i = s; i < e; i++) {
        int c = g_col[i];
        const float* row = h + (size_t)c * CH;
        #pragma unroll
        for (int v = 0; v < V; v++) {
            float4 t = __ldg((const float4*)(row + v * 128 + lane * 4));
            acc[v].x += t.x; acc[v].y += t.y; acc[v].z += t.z; acc[v].w += t.w;
        }
    }
    #pragma unroll
    for (int v = 0; v < V; v++)
        *(float4*)(z + (size_t)warp * CH + v * 128 + lane * 4) = acc[v];
}

// ======================================================================
// Tensor-core GEMM: C[M,256] = act(A[M,K] @ B[K,256] + bias)
// bf16 3-term compensated split (A*B ~= Ah*Bh + Ah*Bl + Al*Bh).
// CTA tile 128x128, 8 warps of 32x64, BK=16, mma.sync m16n8k16.
// Double-buffered smem + register prefetch; one syncthreads per K-step.
// ======================================================================
__device__ __forceinline__ void mma_bf16(float* d, uint32_t a0, uint32_t a1,
                                         uint32_t a2, uint32_t a3,
                                         uint32_t b0, uint32_t b1) {
    asm volatile(
        "mma.sync.aligned.m16n8k16.row.col.f32.bf16.bf16.f32 "
        "{%0,%1,%2,%3}, {%4,%5,%6,%7}, {%8,%9}, {%0,%1,%2,%3};\n"
        : "+f"(d[0]), "+f"(d[1]), "+f"(d[2]), "+f"(d[3])
        : "r"(a0), "r"(a1), "r"(a2), "r"(a3), "r"(b0), "r"(b1));
}

__device__ __forceinline__ void split2(float a, float b, uint32_t& hi, uint32_t& lo) {
    __nv_bfloat16 ha = __float2bfloat16(a);
    __nv_bfloat16 hb = __float2bfloat16(b);
    __nv_bfloat16 la = __float2bfloat16(a - __bfloat162float(ha));
    __nv_bfloat16 lb = __float2bfloat16(b - __bfloat162float(hb));
    __nv_bfloat162 h2; h2.x = ha; h2.y = hb;
    __nv_bfloat162 l2; l2.x = la; l2.y = lb;
    hi = *(uint32_t*)&h2;
    lo = *(uint32_t*)&l2;
}

template <int K, int ASEL, int CSEL, bool RELU>
__global__ void __launch_bounds__(256, 2)
mma_gemm_kernel(const float* __restrict__ B, const float* __restrict__ bias) {
    constexpr int N = 256;
    constexpr int KT = K / 16;
    const float* A = bufptr<ASEL>();
    float* C = bufptr<CSEL>();

    __shared__ uint32_t As_h[2][128][9], As_l[2][128][9];
    __shared__ uint32_t Bs_h[2][128][9], Bs_l[2][128][9];   // [n][k-pair]

    int tid  = threadIdx.x;
    int wid  = tid >> 5;
    int lane = tid & 31;
    int gid  = lane >> 2;
    int tig  = lane & 3;

    int m0 = blockIdx.y * 128;
    int n0 = blockIdx.x * 128;
    int wm = (wid & 3) * 32;
    int wn = (wid >> 2) * 64;

    float2 aReg[4];
    float2 bReg[4];

    // ---- prefetch tile 0
    {
        #pragma unroll
        for (int it = 0; it < 4; it++) {
            int idx = tid + it * 256;
            int m   = idx >> 3;
            int kw  = idx & 7;
            aReg[it] = make_float2(0.f, 0.f);
            if (m0 + m < N_NODES)
                aReg[it] = *(const float2*)(A + (size_t)(m0 + m) * K + kw * 2);
            int n    = idx & 127;
            int kwb  = idx >> 7;
            int krow = kwb * 2;
            bReg[it].x = __ldg(B + (size_t)krow * N + n0 + n);
            bReg[it].y = __ldg(B + (size_t)(krow + 1) * N + n0 + n);
        }
        #pragma unroll
        for (int it = 0; it < 4; it++) {
            int idx = tid + it * 256;
            int m   = idx >> 3;
            int kw  = idx & 7;
            uint32_t hi, lo;
            split2(aReg[it].x, aReg[it].y, hi, lo);
            As_h[0][m][kw] = hi;
            As_l[0][m][kw] = lo;
            int n   = idx & 127;
            int kwb = idx >> 7;
            split2(bReg[it].x, bReg[it].y, hi, lo);
            Bs_h[0][n][kwb] = hi;
            Bs_l[0][n][kwb] = lo;
        }
    }
    __syncthreads();

    float acc[2][8][4];
    #pragma unroll
    for (int mt = 0; mt < 2; mt++)
        #pragma unroll
        for (int nt = 0; nt < 8; nt++)
            #pragma unroll
            for (int r = 0; r < 4; r++) acc[mt][nt][r] = 0.f;

    for (int kt = 0; kt < KT; kt++) {
        int p = kt & 1;
        if (kt + 1 < KT) {
            #pragma unroll
            for (int it = 0; it < 4; it++) {
                int idx = tid + it * 256;
                int m   = idx >> 3;
                int kw  = idx & 7;
                aReg[it] = make_float2(0.f, 0.f);
                if (m0 + m < N_NODES)
                    aReg[it] = *(const float2*)(A + (size_t)(m0 + m) * K + (kt + 1) * 16 + kw * 2);
                int n    = idx & 127;
                int kwb  = idx >> 7;
                int krow = (kt + 1) * 16 + kwb * 2;
                bReg[it].x = __ldg(B + (size_t)krow * N + n0 + n);
                bReg[it].y = __ldg(B + (size_t)(krow + 1) * N + n0 + n);
            }
        }

        uint32_t ah[2][4], al[2][4];
        #pragma unroll
        for (int mt = 0; mt < 2; mt++) {
            int r = wm + mt * 16;
            ah[mt][0] = As_h[p][r + gid][tig];
            ah[mt][1] = As_h[p][r + 8 + gid][tig];
            ah[mt][2] = As_h[p][r + gid][tig + 4];
            ah[mt][3] = As_h[p][r + 8 + gid][tig + 4];
            al[mt][0] = As_l[p][r + gid][tig];
            al[mt][1] = As_l[p][r + 8 + gid][tig];
            al[mt][2] = As_l[p][r + gid][tig + 4];
            al[mt][3] = As_l[p][r + 8 + gid][tig + 4];
        }
        #pragma unroll
        for (int nt = 0; nt < 8; nt++) {
            int c = wn + nt * 8 + gid;
            uint32_t bh0 = Bs_h[p][c][tig], bh1 = Bs_h[p][c][tig + 4];
            uint32_t bl0 = Bs_l[p][c][tig], bl1 = Bs_l[p][c][tig + 4];
            #pragma unroll
            for (int mt = 0; mt < 2; mt++) {
                mma_bf16(acc[mt][nt], ah[mt][0], ah[mt][1], ah[mt][2], ah[mt][3], bh0, bh1);
                mma_bf16(acc[mt][nt], al[mt][0], al[mt][1], al[mt][2], al[mt][3], bh0, bh1);
                mma_bf16(acc[mt][nt], ah[mt][0], ah[mt][1], ah[mt][2], ah[mt][3], bl0, bl1);
            }
        }

        if (kt + 1 < KT) {
            int q = 1 - p;
            #pragma unroll
            for (int it = 0; it < 4; it++) {
                int idx = tid + it * 256;
                int m   = idx >> 3;
                int kw  = idx & 7;
                uint32_t hi, lo;
                split2(aReg[it].x, aReg[it].y, hi, lo);
                As_h[q][m][kw] = hi;
                As_l[q][m][kw] = lo;
                int n   = idx & 127;
                int kwb = idx >> 7;
                split2(bReg[it].x, bReg[it].y, hi, lo);
                Bs_h[q][n][kwb] = hi;
                Bs_l[q][n][kwb] = lo;
            }
        }
        __syncthreads();
    }

    #pragma unroll
    for (int nt = 0; nt < 8; nt++) {
        int c = n0 + wn + nt * 8 + tig * 2;
        float bv0 = bias[c], bv1 = bias[c + 1];
        #pragma unroll
        for (int mt = 0; mt < 2; mt++) {
            int r0 = m0 + wm + mt * 16 + gid;
            int r1 = r0 + 8;
            float d0 = acc[mt][nt][0] + bv0;
            float d1 = acc[mt][nt][1] + bv1;
            float d2 = acc[mt][nt][2] + bv0;
            float d3 = acc[mt][nt][3] + bv1;
            if (RELU) {
                d0 = fmaxf(d0, 0.f); d1 = fmaxf(d1, 0.f);
                d2 = fmaxf(d2, 0.f); d3 = fmaxf(d3, 0.f);
            }
            if (r0 < N_NODES) *(float2*)(C + (size_t)r0 * N + c) = make_float2(d0, d1);
            if (r1 < N_NODES) *(float2*)(C + (size_t)r1 * N + c) = make_float2(d2, d3);
        }
    }
}

// ---------------- fp32 SIMT GEMM for readout (K=512 cat, N=40) ----------------
__global__ void __launch_bounds__(256)
readout_gemm_kernel(const float* __restrict__ B, const float* __restrict__ bias) {
    constexpr int K = 512, N = OUT_CH;
    float* C = bufptr<0>();

    __shared__ float As[16][128];
    __shared__ float Bs[16][64];
    int tid = threadIdx.x;
    int tx = tid & 15;
    int ty = tid >> 4;
    int m0 = blockIdx.y * 128;

    float acc[8][4];
    #pragma unroll
    for (int i = 0; i < 8; i++)
        #pragma unroll
        for (int j = 0; j < 4; j++) acc[i][j] = 0.f;

    for (int kt = 0; kt < K / 16; kt++) {
        #pragma unroll
        for (int l = 0; l < 2; l++) {
            int idx = tid + l * 256;
            int row = idx >> 2;
            int c4  = (idx & 3) * 4;
            int m = m0 + row;
            int kk = kt * 16 + c4;
            float4 v = make_float4(0.f, 0.f, 0.f, 0.f);
            if (m < N_NODES) {
                const float* srcp = (kk < 256)
                    ? ((const float*)g_h1 + (size_t)m * 256 + kk)
                    : ((const float*)g_h2 + (size_t)m * 256 + (kk - 256));
                v = *(const float4*)srcp;
            }
            As[c4 + 0][row] = v.x;
            As[c4 + 1][row] = v.y;
            As[c4 + 2][row] = v.z;
            As[c4 + 3][row] = v.w;
        }
        {
            int r  = tid >> 4;
            int c4 = (tid & 15) * 4;
            float4 v = make_float4(0.f, 0.f, 0.f, 0.f);
            if (c4 < N) v = *(const float4*)(B + (size_t)(kt * 16 + r) * N + c4);
            *(float4*)&Bs[r][c4] = v;
        }
        __syncthreads();

        #pragma unroll
        for (int k = 0; k < 16; k++) {
            float4 a0 = *(const float4*)&As[k][ty * 8];
            float4 a1 = *(const float4*)&As[k][ty * 8 + 4];
            float4 b  = *(const float4*)&Bs[k][tx * 4];
            float ar[8] = {a0.x, a0.y, a0.z, a0.w, a1.x, a1.y, a1.z, a1.w};
            float br[4] = {b.x, b.y, b.z, b.w};
            #pragma unroll
            for (int i = 0; i < 8; i++)
                #pragma unroll
                for (int j = 0; j < 4; j++)
                    acc[i][j] += ar[i] * br[j];
        }
        __syncthreads();
    }

    int colBase = tx * 4;
    float4 bv = make_float4(0.f, 0.f, 0.f, 0.f);
    if (colBase < N) bv = *(const float4*)(bias + colBase);
    #pragma unroll
    for (int i = 0; i < 8; i++) {
        int m = m0 + ty * 8 + i;
        if (m < N_NODES && colBase < N) {
            float4 o;
            o.x = acc[i][0] + bv.x;
            o.y = acc[i][1] + bv.y;
            o.z = acc[i][2] + bv.z;
            o.w = acc[i][3] + bv.w;
            *(float4*)(C + (size_t)m * N + colBase) = o;
        }
    }
}

// ---------------- log_softmax over 40 logits, one thread per node ----------------
__global__ void logsoftmax_kernel(float* __restrict__ out) {
    int n = blockIdx.x * blockDim.x + threadIdx.x;
    if (n >= N_NODES) return;
    const float* row = (const float*)g_z + (size_t)n * OUT_CH;
    float m = -3.0e38f;
    #pragma unroll
    for (int c = 0; c < OUT_CH; c++) m = fmaxf(m, row[c]);
    float s = 0.f;
    #pragma unroll
    for (int c = 0; c < OUT_CH; c++) s += expf(row[c] - m);
    float lse = m + logf(s);
    float* o = out + (size_t)n * OUT_CH;
    #pragma unroll
    for (int c = 0; c < OUT_CH; c++) o[c] = row[c] - lse;
}

// ---------------- launch ----------------
extern "C" void kernel_launch(void* const* d_in, const int* in_sizes, int n_in,
                              void* d_out, int out_size) {
    const float* x    = (const float*)d_in[0];
    const void*  ei   = (const void*)d_in[1];
    const float* W1a  = (const float*)d_in[2];
    const float* b1a  = (const float*)d_in[3];
    const float* W2a  = (const float*)d_in[4];
    const float* b2a  = (const float*)d_in[5];
    const float* W1b  = (const float*)d_in[6];
    const float* b1b  = (const float*)d_in[7];
    const float* W2b  = (const float*)d_in[8];
    const float* b2b  = (const float*)d_in[9];
    const float* Wlin = (const float*)d_in[10];
    const float* blin = (const float*)d_in[11];
    float* out = (float*)d_out;

    detect_kernel<<<1, 256>>>((const long long*)ei);

    // CSR build (int atomics only; all edge reads go through load_edge)
    zero_deg_kernel<<<(N_NODES + 255) / 256, 256>>>();
    hist_kernel<<<(N_EDGES + 255) / 256, 256>>>(ei);
    scan_kernel<<<1, 1024>>>();
    csr_scatter_kernel<<<(N_EDGES + 255) / 256, 256>>>(ei);

    dim3 mmaGrid(2, (N_NODES + 127) / 128);
    dim3 linGrid(1, (N_NODES + 127) / 128);
    int aggBlocks = (N_NODES + 7) / 8;   // 8 warps/block, warp per node

    // ---- layer 1
    agg_kernel<IN_CH, -1, 0><<<aggBlocks, 256>>>(x);
    mma_gemm_kernel<IN_CH, 0, 1, true><<<mmaGrid, 256>>>(W1a, b1a);
    mma_gemm_kernel<HID,   1, 2, true><<<mmaGrid, 256>>>(W2a, b2a);

    // ---- layer 2
    agg_kernel<HID, 2, 0><<<aggBlocks, 256>>>(nullptr);
    mma_gemm_kernel<HID, 0, 1, true><<<mmaGrid, 256>>>(W1b, b1b);
    mma_gemm_kernel<HID, 1, 3, true><<<mmaGrid, 256>>>(W2b, b2b);

    // ---- readout + softmax
    readout_gemm_kernel<<<linGrid, 256>>>(Wlin, blin);
    logsoftmax_kernel<<<(N_NODES + 255) / 256, 256>>>(out);
}